// round 2
// baseline (speedup 1.0000x reference)
#include <cuda_runtime.h>
#include <math.h>
#include <stdint.h>

#define D_MODEL 1024
#define FF_DIM  4096
#define NTOK    4096   // B*S = 2*2048
#define SEQ     2048
#define NHEADS  16
#define DHEAD   64
#define EPSLN   1e-5f

// ---------------- scratch (static device globals; no allocation) -------------
__device__ float g_h  [NTOK * D_MODEL];   // LN output (reused for LN1 and LN2)
__device__ float g_q  [NTOK * D_MODEL];
__device__ float g_k  [NTOK * D_MODEL];
__device__ float g_v  [NTOK * D_MODEL];
__device__ float g_ctx[NTOK * D_MODEL];
__device__ float g_x1 [NTOK * D_MODEL];   // after residual 1
__device__ float g_ff [NTOK * FF_DIM];    // relu(h @ w1 + b1)

// ---------------- LayerNorm: one block per row, float4 vectorized ------------
__global__ void ln_kernel(const float* __restrict__ x,
                          const float* __restrict__ g,
                          const float* __restrict__ b,
                          float* __restrict__ out) {
    int row = blockIdx.x;
    const float4* xr = (const float4*)(x + (size_t)row * D_MODEL);
    float4 v = xr[threadIdx.x];               // 256 threads * 4 = 1024
    float sum   = v.x + v.y + v.z + v.w;
    float sumsq = v.x * v.x + v.y * v.y + v.z * v.z + v.w * v.w;
    #pragma unroll
    for (int o = 16; o > 0; o >>= 1) {
        sum   += __shfl_xor_sync(0xffffffffu, sum, o);
        sumsq += __shfl_xor_sync(0xffffffffu, sumsq, o);
    }
    __shared__ float s1[8], s2[8];
    int w = threadIdx.x >> 5, l = threadIdx.x & 31;
    if (l == 0) { s1[w] = sum; s2[w] = sumsq; }
    __syncthreads();
    float ts = 0.f, tq = 0.f;
    #pragma unroll
    for (int i = 0; i < 8; i++) { ts += s1[i]; tq += s2[i]; }
    float mu   = ts * (1.0f / D_MODEL);
    float var  = tq * (1.0f / D_MODEL) - mu * mu;
    float rstd = rsqrtf(var + EPSLN);
    float4 gv = ((const float4*)g)[threadIdx.x];
    float4 bv = ((const float4*)b)[threadIdx.x];
    float4 ov;
    ov.x = (v.x - mu) * rstd * gv.x + bv.x;
    ov.y = (v.y - mu) * rstd * gv.y + bv.y;
    ov.z = (v.z - mu) * rstd * gv.z + bv.z;
    ov.w = (v.w - mu) * rstd * gv.w + bv.w;
    ((float4*)(out + (size_t)row * D_MODEL))[threadIdx.x] = ov;
}

// ---------------- SGEMM: C = A[M,K] @ B[K,N] + bias (+res) (relu) ------------
// BM=BN=128, BK=16, 256 threads, 8x8 per thread. M,N,K all multiples of tile.
template<int RELU, int RES>
__global__ void __launch_bounds__(256, 2)
gemm_kernel(const float* __restrict__ A, const float* __restrict__ B,
            const float* __restrict__ bias, const float* __restrict__ res,
            float* __restrict__ C, int M, int N, int K) {
    __shared__ float As[16][132];   // transposed A tile, padded
    __shared__ float Bs[16][128];

    int tid = threadIdx.x;
    int tx = tid & 15, ty = tid >> 4;
    const float* Ablk = A + (size_t)blockIdx.y * 128 * K;
    const float* Bblk = B + (size_t)blockIdx.x * 128;

    float acc[8][8];
    #pragma unroll
    for (int i = 0; i < 8; i++)
        #pragma unroll
        for (int j = 0; j < 8; j++) acc[i][j] = 0.f;

    for (int k0 = 0; k0 < K; k0 += 16) {
        #pragma unroll
        for (int i = 0; i < 2; i++) {
            int idx = tid + i * 256;             // 0..511
            int row = idx >> 2, c4 = (idx & 3) * 4;
            float4 va = *(const float4*)(Ablk + (size_t)row * K + k0 + c4);
            As[c4 + 0][row] = va.x; As[c4 + 1][row] = va.y;
            As[c4 + 2][row] = va.z; As[c4 + 3][row] = va.w;
        }
        #pragma unroll
        for (int i = 0; i < 2; i++) {
            int idx = tid + i * 256;
            int kk = idx >> 5, n4 = (idx & 31) * 4;
            *(float4*)(&Bs[kk][n4]) =
                *(const float4*)(Bblk + (size_t)(k0 + kk) * N + n4);
        }
        __syncthreads();
        #pragma unroll
        for (int kk = 0; kk < 16; kk++) {
            float a[8], b[8];
            #pragma unroll
            for (int i = 0; i < 8; i++) a[i] = As[kk][ty * 8 + i];
            #pragma unroll
            for (int j = 0; j < 8; j++) b[j] = Bs[kk][tx * 8 + j];
            #pragma unroll
            for (int i = 0; i < 8; i++)
                #pragma unroll
                for (int j = 0; j < 8; j++) acc[i][j] += a[i] * b[j];
        }
        __syncthreads();
    }

    #pragma unroll
    for (int i = 0; i < 8; i++) {
        int row = blockIdx.y * 128 + ty * 8 + i;
        #pragma unroll
        for (int j = 0; j < 8; j++) {
            int col = blockIdx.x * 128 + tx * 8 + j;
            float v = acc[i][j] + bias[col];
            if (RES)  v += res[(size_t)row * N + col];
            if (RELU) v = fmaxf(v, 0.f);
            C[(size_t)row * N + col] = v;
        }
    }
}

// ---------------- Flash attention -------------------------------------------
// Q/K/V stored as [NTOK, D_MODEL] with head h at columns h*64..h*64+63.
// grid = (SEQ/64, B*NHEADS), 256 threads, 64x64 tiles, online softmax.
#define FLASH_SMEM (( (64*64) + (64*65) + (64*65) + 3*64 + 64 ) * 4)

__global__ void flash_kernel(const float* __restrict__ Q,
                             const float* __restrict__ K,
                             const float* __restrict__ V,
                             const int*   __restrict__ mask,
                             float* __restrict__ O) {
    extern __shared__ float sm[];
    float* Qs   = sm;                 // [64][64]  row-major, stride 64
    float* KVs  = Qs  + 64 * 64;      // [65-strided] K^T then V
    float* Ps   = KVs + 64 * 65;      // [64][65]
    float* rowm = Ps  + 64 * 65;      // 64
    float* rowl = rowm + 64;          // 64
    float* rowa = rowl + 64;          // 64
    int*   msk  = (int*)(rowa + 64);  // 64

    int tid = threadIdx.x;
    int bh = blockIdx.y;
    int b = bh >> 4, h = bh & 15;
    int q0 = blockIdx.x * 64;

    const float* Qbase = Q + ((size_t)b * SEQ) * D_MODEL + h * DHEAD;
    const float* Kbase = K + ((size_t)b * SEQ) * D_MODEL + h * DHEAD;
    const float* Vbase = V + ((size_t)b * SEQ) * D_MODEL + h * DHEAD;

    // load Q tile (float4, stride-64 rows)
    for (int idx = tid; idx < 1024; idx += 256) {
        int r = idx >> 4, c4 = (idx & 15) * 4;
        float4 v = *(const float4*)(Qbase + (size_t)(q0 + r) * D_MODEL + c4);
        float* d = &Qs[r * 64 + c4];
        d[0] = v.x; d[1] = v.y; d[2] = v.z; d[3] = v.w;
    }
    if (tid < 64) { rowm[tid] = -1e30f; rowl[tid] = 0.f; }

    int r = tid >> 4, c = tid & 15;
    int i0 = r * 4, j0 = c * 4;
    float accv[4][4];
    #pragma unroll
    for (int i = 0; i < 4; i++)
        #pragma unroll
        for (int j = 0; j < 4; j++) accv[i][j] = 0.f;

    __syncthreads();

    for (int kv0 = 0; kv0 < SEQ; kv0 += 64) {
        // load K tile transposed: KVs[d*65 + j]
        for (int idx = tid; idx < 1024; idx += 256) {
            int rr = idx >> 4, c4 = (idx & 15) * 4;
            float4 v = *(const float4*)(Kbase + (size_t)(kv0 + rr) * D_MODEL + c4);
            KVs[(c4 + 0) * 65 + rr] = v.x;
            KVs[(c4 + 1) * 65 + rr] = v.y;
            KVs[(c4 + 2) * 65 + rr] = v.z;
            KVs[(c4 + 3) * 65 + rr] = v.w;
        }
        if (tid < 64) msk[tid] = mask[b * SEQ + kv0 + tid];
        __syncthreads();

        // S = Q @ K^T * scale  -> Ps
        float s[4][4];
        #pragma unroll
        for (int i = 0; i < 4; i++)
            #pragma unroll
            for (int j = 0; j < 4; j++) s[i][j] = 0.f;
        for (int d = 0; d < 64; d++) {
            float qv[4], kv[4];
            #pragma unroll
            for (int i = 0; i < 4; i++) qv[i] = Qs[(i0 + i) * 64 + d];
            #pragma unroll
            for (int j = 0; j < 4; j++) kv[j] = KVs[d * 65 + j0 + j];
            #pragma unroll
            for (int i = 0; i < 4; i++)
                #pragma unroll
                for (int j = 0; j < 4; j++) s[i][j] += qv[i] * kv[j];
        }
        #pragma unroll
        for (int i = 0; i < 4; i++)
            #pragma unroll
            for (int j = 0; j < 4; j++)
                Ps[(i0 + i) * 65 + j0 + j] = s[i][j] * 0.125f;
        __syncthreads();

        // online softmax: one thread per row
        if (tid < 64) {
            float* pr = Ps + tid * 65;
            float mold = rowm[tid];
            float mt = mold;
            #pragma unroll 8
            for (int j = 0; j < 64; j++) {
                float sv = msk[j] ? pr[j] : -1e30f;
                pr[j] = sv;
                mt = fmaxf(mt, sv);
            }
            float alpha = __expf(mold - mt);
            float ls = 0.f;
            #pragma unroll 8
            for (int j = 0; j < 64; j++) {
                float p = __expf(pr[j] - mt);
                pr[j] = p;
                ls += p;
            }
            rowl[tid] = rowl[tid] * alpha + ls;
            rowm[tid] = mt;
            rowa[tid] = alpha;
        }
        // load V tile (overwrites K region; S compute already done & synced)
        for (int idx = tid; idx < 1024; idx += 256) {
            int rr = idx >> 4, c4 = (idx & 15) * 4;
            float4 v = *(const float4*)(Vbase + (size_t)(kv0 + rr) * D_MODEL + c4);
            KVs[rr * 65 + c4 + 0] = v.x;
            KVs[rr * 65 + c4 + 1] = v.y;
            KVs[rr * 65 + c4 + 2] = v.z;
            KVs[rr * 65 + c4 + 3] = v.w;
        }
        __syncthreads();

        // rescale O and accumulate P @ V
        float al[4];
        #pragma unroll
        for (int i = 0; i < 4; i++) al[i] = rowa[i0 + i];
        #pragma unroll
        for (int i = 0; i < 4; i++)
            #pragma unroll
            for (int j = 0; j < 4; j++) accv[i][j] *= al[i];
        for (int jk = 0; jk < 64; jk++) {
            float pv[4], vv[4];
            #pragma unroll
            for (int i = 0; i < 4; i++) pv[i] = Ps[(i0 + i) * 65 + jk];
            #pragma unroll
            for (int u = 0; u < 4; u++) vv[u] = KVs[jk * 65 + j0 + u];
            #pragma unroll
            for (int i = 0; i < 4; i++)
                #pragma unroll
                for (int u = 0; u < 4; u++) accv[i][u] += pv[i] * vv[u];
        }
        __syncthreads();   // before next K tile overwrites KVs / Ps
    }

    float linv[4];
    #pragma unroll
    for (int i = 0; i < 4; i++) linv[i] = 1.f / rowl[i0 + i];
    float* Obase = O + ((size_t)(b * SEQ + q0)) * D_MODEL + h * DHEAD;
    #pragma unroll
    for (int i = 0; i < 4; i++)
        #pragma unroll
        for (int j = 0; j < 4; j++)
            Obase[(size_t)(i0 + i) * D_MODEL + j0 + j] = accv[i][j] * linv[i];
}

// ---------------- launch ------------------------------------------------------
extern "C" void kernel_launch(void* const* d_in, const int* in_sizes, int n_in,
                              void* d_out, int out_size) {
    const float* x    = (const float*)d_in[0];
    const int*   mask = (const int*)  d_in[1];
    const float* wq   = (const float*)d_in[2];
    const float* bq   = (const float*)d_in[3];
    const float* wk   = (const float*)d_in[4];
    const float* bk   = (const float*)d_in[5];
    const float* wv   = (const float*)d_in[6];
    const float* bv   = (const float*)d_in[7];
    const float* wo   = (const float*)d_in[8];
    const float* bo   = (const float*)d_in[9];
    const float* ln1g = (const float*)d_in[10];
    const float* ln1b = (const float*)d_in[11];
    const float* ln2g = (const float*)d_in[12];
    const float* ln2b = (const float*)d_in[13];
    const float* w1   = (const float*)d_in[14];
    const float* b1   = (const float*)d_in[15];
    const float* w2   = (const float*)d_in[16];
    const float* b2   = (const float*)d_in[17];
    float* out = (float*)d_out;

    float *ph, *pq, *pk, *pv, *pctx, *px1, *pff;
    cudaGetSymbolAddress((void**)&ph,   g_h);
    cudaGetSymbolAddress((void**)&pq,   g_q);
    cudaGetSymbolAddress((void**)&pk,   g_k);
    cudaGetSymbolAddress((void**)&pv,   g_v);
    cudaGetSymbolAddress((void**)&pctx, g_ctx);
    cudaGetSymbolAddress((void**)&px1,  g_x1);
    cudaGetSymbolAddress((void**)&pff,  g_ff);

    // LN1
    ln_kernel<<<NTOK, 256>>>(x, ln1g, ln1b, ph);

    // Q/K/V projections
    dim3 gqkv(D_MODEL / 128, NTOK / 128);
    gemm_kernel<0, 0><<<gqkv, 256>>>(ph, wq, bq, nullptr, pq, NTOK, D_MODEL, D_MODEL);
    gemm_kernel<0, 0><<<gqkv, 256>>>(ph, wk, bk, nullptr, pk, NTOK, D_MODEL, D_MODEL);
    gemm_kernel<0, 0><<<gqkv, 256>>>(ph, wv, bv, nullptr, pv, NTOK, D_MODEL, D_MODEL);

    // attention
    cudaFuncSetAttribute(flash_kernel,
                         cudaFuncAttributeMaxDynamicSharedMemorySize, FLASH_SMEM);
    dim3 gfa(SEQ / 64, 2 * NHEADS);
    flash_kernel<<<gfa, 256, FLASH_SMEM>>>(pq, pk, pv, mask, pctx);

    // O projection + residual 1
    gemm_kernel<0, 1><<<gqkv, 256>>>(pctx, wo, bo, x, px1, NTOK, D_MODEL, D_MODEL);

    // LN2
    ln_kernel<<<NTOK, 256>>>(px1, ln2g, ln2b, ph);

    // FF1 (relu)
    dim3 gff1(FF_DIM / 128, NTOK / 128);
    gemm_kernel<1, 0><<<gff1, 256>>>(ph, w1, b1, nullptr, pff, NTOK, FF_DIM, D_MODEL);

    // FF2 + residual 2 -> out
    dim3 gff2(D_MODEL / 128, NTOK / 128);
    gemm_kernel<0, 1><<<gff2, 256>>>(pff, w2, b2, px1, out, NTOK, D_MODEL, FF_DIM);
}

// round 4
// speedup vs baseline: 1.7964x; 1.7964x over previous
#include <cuda_runtime.h>
#include <cuda_bf16.h>
#include <math.h>
#include <stdint.h>

#define D_MODEL 1024
#define FF_DIM  4096
#define NTOK    4096
#define SEQ     2048
#define NHEADS  16
#define DHEAD   64
#define EPSLN   1e-5f

typedef __nv_bfloat16 bf16;
typedef __nv_bfloat162 bf162;

// ---------------- scratch ----------------------------------------------------
__device__ bf16  g_hh[NTOK * D_MODEL], g_hl[NTOK * D_MODEL];
__device__ float g_q [NTOK * D_MODEL], g_k [NTOK * D_MODEL], g_v [NTOK * D_MODEL];
__device__ bf16  g_ch[NTOK * D_MODEL], g_cl[NTOK * D_MODEL];
__device__ float g_x1[NTOK * D_MODEL];
__device__ bf16  g_fh[NTOK * FF_DIM],  g_fl[NTOK * FF_DIM];
__device__ bf16  g_wqh[D_MODEL*D_MODEL], g_wql[D_MODEL*D_MODEL];
__device__ bf16  g_wkh[D_MODEL*D_MODEL], g_wkl[D_MODEL*D_MODEL];
__device__ bf16  g_wvh[D_MODEL*D_MODEL], g_wvl[D_MODEL*D_MODEL];
__device__ bf16  g_woh[D_MODEL*D_MODEL], g_wol[D_MODEL*D_MODEL];
__device__ bf16  g_w1h[D_MODEL*FF_DIM],  g_w1l[D_MODEL*FF_DIM];
__device__ bf16  g_w2h[FF_DIM*D_MODEL],  g_w2l[FF_DIM*D_MODEL];

// ---------------- PTX helpers ------------------------------------------------
__device__ __forceinline__ void split2(float v, bf16& h, bf16& l) {
    h = __float2bfloat16(v);
    l = __float2bfloat16(v - __bfloat162float(h));
}
__device__ __forceinline__ void ldsm_x4(uint32_t* r, uint32_t a) {
    asm volatile("ldmatrix.sync.aligned.m8n8.x4.shared.b16 {%0,%1,%2,%3},[%4];"
                 : "=r"(r[0]), "=r"(r[1]), "=r"(r[2]), "=r"(r[3]) : "r"(a));
}
__device__ __forceinline__ void ldsm_x4t(uint32_t* r, uint32_t a) {
    asm volatile("ldmatrix.sync.aligned.m8n8.x4.trans.shared.b16 {%0,%1,%2,%3},[%4];"
                 : "=r"(r[0]), "=r"(r[1]), "=r"(r[2]), "=r"(r[3]) : "r"(a));
}
__device__ __forceinline__ void mma16816(float* d, const uint32_t* a, const uint32_t* b) {
    asm volatile("mma.sync.aligned.m16n8k16.row.col.f32.bf16.bf16.f32 "
                 "{%0,%1,%2,%3},{%4,%5,%6,%7},{%8,%9},{%0,%1,%2,%3};"
                 : "+f"(d[0]), "+f"(d[1]), "+f"(d[2]), "+f"(d[3])
                 : "r"(a[0]), "r"(a[1]), "r"(a[2]), "r"(a[3]), "r"(b[0]), "r"(b[1]));
}
__device__ __forceinline__ void cp16(uint32_t s, const void* g) {
    asm volatile("cp.async.cg.shared.global [%0],[%1],16;" :: "r"(s), "l"(g));
}
__device__ __forceinline__ void cp_commit() { asm volatile("cp.async.commit_group;"); }
template<int N> __device__ __forceinline__ void cp_wait() {
    asm volatile("cp.async.wait_group %0;" :: "n"(N));
}

// ---------------- split (weights) -------------------------------------------
__global__ void split_kernel(const float* __restrict__ in,
                             bf16* __restrict__ hi, bf16* __restrict__ lo, int n4) {
    int i = blockIdx.x * 256 + threadIdx.x;
    if (i >= n4) return;
    float4 v = ((const float4*)in)[i];
    bf16 h0,h1,h2,h3,l0,l1,l2,l3;
    split2(v.x,h0,l0); split2(v.y,h1,l1); split2(v.z,h2,l2); split2(v.w,h3,l3);
    bf162 H0; H0.x=h0; H0.y=h1;  bf162 H1; H1.x=h2; H1.y=h3;
    bf162 L0; L0.x=l0; L0.y=l1;  bf162 L1; L1.x=l2; L1.y=l3;
    ((bf162*)hi)[i*2] = H0; ((bf162*)hi)[i*2+1] = H1;
    ((bf162*)lo)[i*2] = L0; ((bf162*)lo)[i*2+1] = L1;
}

// ---------------- LayerNorm -> bf16 hi/lo ------------------------------------
__global__ void ln_split_kernel(const float* __restrict__ x,
                                const float* __restrict__ g,
                                const float* __restrict__ b,
                                bf16* __restrict__ hi, bf16* __restrict__ lo) {
    int row = blockIdx.x;
    const float4* xr = (const float4*)(x + (size_t)row * D_MODEL);
    float4 v = xr[threadIdx.x];
    float sum   = v.x + v.y + v.z + v.w;
    float sumsq = v.x*v.x + v.y*v.y + v.z*v.z + v.w*v.w;
    #pragma unroll
    for (int o = 16; o > 0; o >>= 1) {
        sum   += __shfl_xor_sync(0xffffffffu, sum, o);
        sumsq += __shfl_xor_sync(0xffffffffu, sumsq, o);
    }
    __shared__ float s1[8], s2[8];
    int w = threadIdx.x >> 5, l = threadIdx.x & 31;
    if (l == 0) { s1[w] = sum; s2[w] = sumsq; }
    __syncthreads();
    float ts = 0.f, tq = 0.f;
    #pragma unroll
    for (int i = 0; i < 8; i++) { ts += s1[i]; tq += s2[i]; }
    float mu   = ts * (1.0f / D_MODEL);
    float var  = tq * (1.0f / D_MODEL) - mu * mu;
    float rstd = rsqrtf(var + EPSLN);
    float4 gv = ((const float4*)g)[threadIdx.x];
    float4 bv = ((const float4*)b)[threadIdx.x];
    float o0 = (v.x-mu)*rstd*gv.x + bv.x;
    float o1 = (v.y-mu)*rstd*gv.y + bv.y;
    float o2 = (v.z-mu)*rstd*gv.z + bv.z;
    float o3 = (v.w-mu)*rstd*gv.w + bv.w;
    bf16 h0,h1,h2,h3,l0,l1,l2,l3;
    split2(o0,h0,l0); split2(o1,h1,l1); split2(o2,h2,l2); split2(o3,h3,l3);
    size_t base2 = ((size_t)row * D_MODEL) / 2 + threadIdx.x * 2;
    bf162 H0; H0.x=h0; H0.y=h1;  bf162 H1; H1.x=h2; H1.y=h3;
    bf162 L0; L0.x=l0; L0.y=l1;  bf162 L1; L1.x=l2; L1.y=l3;
    ((bf162*)hi)[base2] = H0; ((bf162*)hi)[base2+1] = H1;
    ((bf162*)lo)[base2] = L0; ((bf162*)lo)[base2+1] = L1;
}

// ---------------- tensor-core GEMM (bf16x3 split) ----------------------------
// C = A @ B (+bias)(+res)(relu); A hi/lo [M,K], B hi/lo [K,N] bf16 row-major.
// BM=BN=128, BK=32, 256 threads, warp grid 4x2, warp tile 32x64.
#define BMT 128
#define BNT 128
#define BKT 32
#define ASTR 48          // halves per A row in smem
#define BSTR 136         // halves per B row in smem
#define SA_BYTES (BMT * ASTR * 2)                 // 12288
#define SB_BYTES (BKT * BSTR * 2)                 // 8704
#define STAGE_BYTES (2*SA_BYTES + 2*SB_BYTES)     // 41984
#define GEMM_SMEM (2 * STAGE_BYTES)               // 83968

template<int RELU, int RES, int EMITF, int EMITS>
__global__ void __launch_bounds__(256)
gemm_tc(const bf16* __restrict__ Ah, const bf16* __restrict__ Al,
        const bf16* __restrict__ Bh, const bf16* __restrict__ Bl,
        const float* __restrict__ bias, const float* __restrict__ res,
        float* __restrict__ C, bf16* __restrict__ Chi, bf16* __restrict__ Clo,
        int M, int N, int K) {
    extern __shared__ char smr[];
    uint32_t sbase = (uint32_t)__cvta_generic_to_shared(smr);
    int tid = threadIdx.x, lane = tid & 31, warp = tid >> 5;
    int wm = warp >> 1, wn = warp & 1;
    int bm = blockIdx.y, bn = blockIdx.x;
    size_t arow0 = (size_t)bm * BMT;
    int ncol0 = bn * BNT;

    float d[2][8][4];
    #pragma unroll
    for (int i = 0; i < 2; i++)
        #pragma unroll
        for (int j = 0; j < 8; j++)
            #pragma unroll
            for (int q = 0; q < 4; q++) d[i][j][q] = 0.f;

    auto load_stage = [&](int st, int k0) {
        uint32_t s = sbase + st * STAGE_BYTES;
        #pragma unroll
        for (int i = 0; i < 2; i++) {
            int slot = tid + i * 256;
            int r = slot >> 2, q = slot & 3;
            size_t go = (arow0 + r) * K + k0 + q * 8;
            uint32_t so = (uint32_t)(r * ASTR + q * 8) * 2;
            cp16(s + so, Ah + go);
            cp16(s + SA_BYTES + so, Al + go);
        }
        #pragma unroll
        for (int i = 0; i < 2; i++) {
            int slot = tid + i * 256;
            int r = slot >> 4, sg = slot & 15;
            size_t go = (size_t)(k0 + r) * N + ncol0 + sg * 8;
            uint32_t so = (uint32_t)(r * BSTR + sg * 8) * 2;
            cp16(s + 2*SA_BYTES + so, Bh + go);
            cp16(s + 2*SA_BYTES + SB_BYTES + so, Bl + go);
        }
        cp_commit();
    };

    int nK = K / BKT;
    load_stage(0, 0);
    int lr = lane & 15, lc = lane >> 4;

    for (int kt = 0; kt < nK; kt++) {
        if (kt + 1 < nK) { load_stage((kt + 1) & 1, (kt + 1) * BKT); cp_wait<1>(); }
        else             { cp_wait<0>(); }
        __syncthreads();
        uint32_t s   = sbase + (kt & 1) * STAGE_BYTES;
        uint32_t sAh = s, sAl = s + SA_BYTES;
        uint32_t sBh = s + 2*SA_BYTES, sBl = sBh + SB_BYTES;
        #pragma unroll
        for (int ks = 0; ks < BKT; ks += 16) {
            uint32_t fAh[2][4], fAl[2][4];
            #pragma unroll
            for (int mt = 0; mt < 2; mt++) {
                int row = wm * 32 + mt * 16 + lr;
                int col = ks + lc * 8;
                uint32_t off = (uint32_t)(row * ASTR + col) * 2;
                ldsm_x4(fAh[mt], sAh + off);
                ldsm_x4(fAl[mt], sAl + off);
            }
            #pragma unroll
            for (int np = 0; np < 4; np++) {
                int nb = wn * 64 + np * 16;
                uint32_t off = (uint32_t)((ks + lr) * BSTR + nb + lc * 8) * 2;
                uint32_t bh[4], bl[4];
                ldsm_x4t(bh, sBh + off);
                ldsm_x4t(bl, sBl + off);
                #pragma unroll
                for (int mt = 0; mt < 2; mt++) {
                    #pragma unroll
                    for (int nt = 0; nt < 2; nt++) {
                        float* dd = d[mt][np * 2 + nt];
                        mma16816(dd, fAh[mt], &bh[nt * 2]);
                        mma16816(dd, fAl[mt], &bh[nt * 2]);
                        mma16816(dd, fAh[mt], &bl[nt * 2]);
                    }
                }
            }
        }
        __syncthreads();
    }

    // epilogue
    int g = lane >> 2, t = lane & 3;
    #pragma unroll
    for (int mt = 0; mt < 2; mt++) {
        #pragma unroll
        for (int nt = 0; nt < 8; nt++) {
            int col = ncol0 + wn * 64 + nt * 8 + t * 2;
            float b0 = bias[col], b1 = bias[col + 1];
            #pragma unroll
            for (int hh = 0; hh < 2; hh++) {
                int row = bm * BMT + wm * 32 + mt * 16 + g + hh * 8;
                float v0 = d[mt][nt][hh * 2 + 0] + b0;
                float v1 = d[mt][nt][hh * 2 + 1] + b1;
                if (RES) {
                    float2 rv = *(const float2*)(res + (size_t)row * N + col);
                    v0 += rv.x; v1 += rv.y;
                }
                if (RELU) { v0 = fmaxf(v0, 0.f); v1 = fmaxf(v1, 0.f); }
                if (EMITF)
                    *(float2*)(C + (size_t)row * N + col) = make_float2(v0, v1);
                if (EMITS) {
                    bf16 h0, l0, h1, l1;
                    split2(v0, h0, l0); split2(v1, h1, l1);
                    bf162 H; H.x = h0; H.y = h1;
                    bf162 L; L.x = l0; L.y = l1;
                    *(bf162*)(Chi + (size_t)row * N + col) = H;
                    *(bf162*)(Clo + (size_t)row * N + col) = L;
                }
            }
        }
    }
}

// ---------------- Flash attention (fp32, emits ctx hi/lo) --------------------
#define FLASH_SMEM (((64*64) + (64*65) + (64*65) + 3*64 + 64) * 4)

__global__ void flash_kernel(const float* __restrict__ Q,
                             const float* __restrict__ K,
                             const float* __restrict__ V,
                             const int*   __restrict__ mask,
                             bf16* __restrict__ Ohi, bf16* __restrict__ Olo) {
    extern __shared__ float sm[];
    float* Qs   = sm;
    float* KVs  = Qs  + 64 * 64;
    float* Ps   = KVs + 64 * 65;
    float* rowm = Ps  + 64 * 65;
    float* rowl = rowm + 64;
    float* rowa = rowl + 64;
    int*   msk  = (int*)(rowa + 64);

    int tid = threadIdx.x;
    int bh = blockIdx.y;
    int b = bh >> 4, h = bh & 15;
    int q0 = blockIdx.x * 64;

    const float* Qbase = Q + ((size_t)b * SEQ) * D_MODEL + h * DHEAD;
    const float* Kbase = K + ((size_t)b * SEQ) * D_MODEL + h * DHEAD;
    const float* Vbase = V + ((size_t)b * SEQ) * D_MODEL + h * DHEAD;

    for (int idx = tid; idx < 1024; idx += 256) {
        int r = idx >> 4, c4 = (idx & 15) * 4;
        float4 v = *(const float4*)(Qbase + (size_t)(q0 + r) * D_MODEL + c4);
        float* dd = &Qs[r * 64 + c4];
        dd[0] = v.x; dd[1] = v.y; dd[2] = v.z; dd[3] = v.w;
    }
    if (tid < 64) { rowm[tid] = -1e30f; rowl[tid] = 0.f; }

    int r = tid >> 4, c = tid & 15;
    int i0 = r * 4, j0 = c * 4;
    float accv[4][4];
    #pragma unroll
    for (int i = 0; i < 4; i++)
        #pragma unroll
        for (int j = 0; j < 4; j++) accv[i][j] = 0.f;

    __syncthreads();

    for (int kv0 = 0; kv0 < SEQ; kv0 += 64) {
        for (int idx = tid; idx < 1024; idx += 256) {
            int rr = idx >> 4, c4 = (idx & 15) * 4;
            float4 v = *(const float4*)(Kbase + (size_t)(kv0 + rr) * D_MODEL + c4);
            KVs[(c4 + 0) * 65 + rr] = v.x;
            KVs[(c4 + 1) * 65 + rr] = v.y;
            KVs[(c4 + 2) * 65 + rr] = v.z;
            KVs[(c4 + 3) * 65 + rr] = v.w;
        }
        if (tid < 64) msk[tid] = mask[b * SEQ + kv0 + tid];
        __syncthreads();

        float s[4][4];
        #pragma unroll
        for (int i = 0; i < 4; i++)
            #pragma unroll
            for (int j = 0; j < 4; j++) s[i][j] = 0.f;
        for (int dd = 0; dd < 64; dd++) {
            float qv[4], kv[4];
            #pragma unroll
            for (int i = 0; i < 4; i++) qv[i] = Qs[(i0 + i) * 64 + dd];
            #pragma unroll
            for (int j = 0; j < 4; j++) kv[j] = KVs[dd * 65 + j0 + j];
            #pragma unroll
            for (int i = 0; i < 4; i++)
                #pragma unroll
                for (int j = 0; j < 4; j++) s[i][j] += qv[i] * kv[j];
        }
        #pragma unroll
        for (int i = 0; i < 4; i++)
            #pragma unroll
            for (int j = 0; j < 4; j++)
                Ps[(i0 + i) * 65 + j0 + j] = s[i][j] * 0.125f;
        __syncthreads();

        if (tid < 64) {
            float* pr = Ps + tid * 65;
            float mold = rowm[tid];
            float mt = mold;
            #pragma unroll 8
            for (int j = 0; j < 64; j++) {
                float sv = msk[j] ? pr[j] : -1e30f;
                pr[j] = sv;
                mt = fmaxf(mt, sv);
            }
            float alpha = __expf(mold - mt);
            float ls = 0.f;
            #pragma unroll 8
            for (int j = 0; j < 64; j++) {
                float p = __expf(pr[j] - mt);
                pr[j] = p;
                ls += p;
            }
            rowl[tid] = rowl[tid] * alpha + ls;
            rowm[tid] = mt;
            rowa[tid] = alpha;
        }
        for (int idx = tid; idx < 1024; idx += 256) {
            int rr = idx >> 4, c4 = (idx & 15) * 4;
            float4 v = *(const float4*)(Vbase + (size_t)(kv0 + rr) * D_MODEL + c4);
            KVs[rr * 65 + c4 + 0] = v.x;
            KVs[rr * 65 + c4 + 1] = v.y;
            KVs[rr * 65 + c4 + 2] = v.z;
            KVs[rr * 65 + c4 + 3] = v.w;
        }
        __syncthreads();

        float al[4];
        #pragma unroll
        for (int i = 0; i < 4; i++) al[i] = rowa[i0 + i];
        #pragma unroll
        for (int i = 0; i < 4; i++)
            #pragma unroll
            for (int j = 0; j < 4; j++) accv[i][j] *= al[i];
        for (int jk = 0; jk < 64; jk++) {
            float pv[4], vv[4];
            #pragma unroll
            for (int i = 0; i < 4; i++) pv[i] = Ps[(i0 + i) * 65 + jk];
            #pragma unroll
            for (int u = 0; u < 4; u++) vv[u] = KVs[jk * 65 + j0 + u];
            #pragma unroll
            for (int i = 0; i < 4; i++)
                #pragma unroll
                for (int u = 0; u < 4; u++) accv[i][u] += pv[i] * vv[u];
        }
        __syncthreads();
    }

    float linv[4];
    #pragma unroll
    for (int i = 0; i < 4; i++) linv[i] = 1.f / rowl[i0 + i];
    size_t obase = ((size_t)(b * SEQ + q0)) * D_MODEL + h * DHEAD;
    #pragma unroll
    for (int i = 0; i < 4; i++) {
        #pragma unroll
        for (int j = 0; j < 4; j += 2) {
            float v0 = accv[i][j] * linv[i];
            float v1 = accv[i][j + 1] * linv[i];
            bf16 h0, l0, h1, l1;
            split2(v0, h0, l0); split2(v1, h1, l1);
            bf162 H; H.x = h0; H.y = h1;
            bf162 L; L.x = l0; L.y = l1;
            size_t o = obase + (size_t)(i0 + i) * D_MODEL + j0 + j;
            *(bf162*)(Ohi + o) = H;
            *(bf162*)(Olo + o) = L;
        }
    }
}

// ---------------- launch ------------------------------------------------------
extern "C" void kernel_launch(void* const* d_in, const int* in_sizes, int n_in,
                              void* d_out, int out_size) {
    const float* x    = (const float*)d_in[0];
    const int*   mask = (const int*)  d_in[1];
    const float* wq   = (const float*)d_in[2];
    const float* bq   = (const float*)d_in[3];
    const float* wk   = (const float*)d_in[4];
    const float* bk   = (const float*)d_in[5];
    const float* wv   = (const float*)d_in[6];
    const float* bv   = (const float*)d_in[7];
    const float* wo   = (const float*)d_in[8];
    const float* bo   = (const float*)d_in[9];
    const float* ln1g = (const float*)d_in[10];
    const float* ln1b = (const float*)d_in[11];
    const float* ln2g = (const float*)d_in[12];
    const float* ln2b = (const float*)d_in[13];
    const float* w1   = (const float*)d_in[14];
    const float* b1   = (const float*)d_in[15];
    const float* w2   = (const float*)d_in[16];
    const float* b2   = (const float*)d_in[17];
    float* out = (float*)d_out;

    bf16 *hh, *hl, *ch, *cl, *fh, *fl;
    bf16 *wqh, *wql, *wkh, *wkl, *wvh, *wvl, *woh, *wol, *w1h, *w1l, *w2h, *w2l;
    float *pq, *pk, *pv, *px1;
    cudaGetSymbolAddress((void**)&hh, g_hh);   cudaGetSymbolAddress((void**)&hl, g_hl);
    cudaGetSymbolAddress((void**)&ch, g_ch);   cudaGetSymbolAddress((void**)&cl, g_cl);
    cudaGetSymbolAddress((void**)&fh, g_fh);   cudaGetSymbolAddress((void**)&fl, g_fl);
    cudaGetSymbolAddress((void**)&wqh, g_wqh); cudaGetSymbolAddress((void**)&wql, g_wql);
    cudaGetSymbolAddress((void**)&wkh, g_wkh); cudaGetSymbolAddress((void**)&wkl, g_wkl);
    cudaGetSymbolAddress((void**)&wvh, g_wvh); cudaGetSymbolAddress((void**)&wvl, g_wvl);
    cudaGetSymbolAddress((void**)&woh, g_woh); cudaGetSymbolAddress((void**)&wol, g_wol);
    cudaGetSymbolAddress((void**)&w1h, g_w1h); cudaGetSymbolAddress((void**)&w1l, g_w1l);
    cudaGetSymbolAddress((void**)&w2h, g_w2h); cudaGetSymbolAddress((void**)&w2l, g_w2l);
    cudaGetSymbolAddress((void**)&pq, g_q);    cudaGetSymbolAddress((void**)&pk, g_k);
    cudaGetSymbolAddress((void**)&pv, g_v);    cudaGetSymbolAddress((void**)&px1, g_x1);

    cudaFuncSetAttribute(gemm_tc<0,0,1,0>, cudaFuncAttributeMaxDynamicSharedMemorySize, GEMM_SMEM);
    cudaFuncSetAttribute(gemm_tc<0,1,1,0>, cudaFuncAttributeMaxDynamicSharedMemorySize, GEMM_SMEM);
    cudaFuncSetAttribute(gemm_tc<1,0,0,1>, cudaFuncAttributeMaxDynamicSharedMemorySize, GEMM_SMEM);
    cudaFuncSetAttribute(flash_kernel, cudaFuncAttributeMaxDynamicSharedMemorySize, FLASH_SMEM);

    // weight splits (every launch; deterministic)
    int n1m4 = D_MODEL * D_MODEL / 4, n4m4 = D_MODEL * FF_DIM / 4;
    split_kernel<<<(n1m4 + 255) / 256, 256>>>(wq, wqh, wql, n1m4);
    split_kernel<<<(n1m4 + 255) / 256, 256>>>(wk, wkh, wkl, n1m4);
    split_kernel<<<(n1m4 + 255) / 256, 256>>>(wv, wvh, wvl, n1m4);
    split_kernel<<<(n1m4 + 255) / 256, 256>>>(wo, woh, wol, n1m4);
    split_kernel<<<(n4m4 + 255) / 256, 256>>>(w1, w1h, w1l, n4m4);
    split_kernel<<<(n4m4 + 255) / 256, 256>>>(w2, w2h, w2l, n4m4);

    // LN1 -> h hi/lo
    ln_split_kernel<<<NTOK, 256>>>(x, ln1g, ln1b, hh, hl);

    // QKV projections (fp32 out)
    dim3 gqkv(D_MODEL / BNT, NTOK / BMT);
    gemm_tc<0,0,1,0><<<gqkv, 256, GEMM_SMEM>>>(hh, hl, wqh, wql, bq, nullptr,
                                               pq, nullptr, nullptr, NTOK, D_MODEL, D_MODEL);
    gemm_tc<0,0,1,0><<<gqkv, 256, GEMM_SMEM>>>(hh, hl, wkh, wkl, bk, nullptr,
                                               pk, nullptr, nullptr, NTOK, D_MODEL, D_MODEL);
    gemm_tc<0,0,1,0><<<gqkv, 256, GEMM_SMEM>>>(hh, hl, wvh, wvl, bv, nullptr,
                                               pv, nullptr, nullptr, NTOK, D_MODEL, D_MODEL);

    // attention -> ctx hi/lo
    dim3 gfa(SEQ / 64, 2 * NHEADS);
    flash_kernel<<<gfa, 256, FLASH_SMEM>>>(pq, pk, pv, mask, ch, cl);

    // O projection + residual 1 -> x1 fp32
    gemm_tc<0,1,1,0><<<gqkv, 256, GEMM_SMEM>>>(ch, cl, woh, wol, bo, x,
                                               px1, nullptr, nullptr, NTOK, D_MODEL, D_MODEL);

    // LN2 -> h hi/lo
    ln_split_kernel<<<NTOK, 256>>>(px1, ln2g, ln2b, hh, hl);

    // FF1 (relu) -> ff hi/lo
    dim3 gff1(FF_DIM / BNT, NTOK / BMT);
    gemm_tc<1,0,0,1><<<gff1, 256, GEMM_SMEM>>>(hh, hl, w1h, w1l, b1, nullptr,
                                               nullptr, fh, fl, NTOK, FF_DIM, D_MODEL);

    // FF2 + residual 2 -> out
    dim3 gff2(D_MODEL / BNT, NTOK / BMT);
    gemm_tc<0,1,1,0><<<gff2, 256, GEMM_SMEM>>>(fh, fl, w2h, w2l, b2, px1,
                                               out, nullptr, nullptr, NTOK, D_MODEL, FF_DIM);
}

// round 5
// speedup vs baseline: 3.0132x; 1.6774x over previous
#include <cuda_runtime.h>
#include <cuda_bf16.h>
#include <math.h>
#include <stdint.h>

#define D_MODEL 1024
#define FF_DIM  4096
#define NTOK    4096
#define SEQ     2048
#define NHEADS  16
#define DHEAD   64
#define EPSLN   1e-5f

typedef __nv_bfloat16 bf16;
typedef __nv_bfloat162 bf162;

// ---------------- scratch ----------------------------------------------------
__device__ bf16  g_hh[NTOK * D_MODEL], g_hl[NTOK * D_MODEL];
__device__ bf16  g_qh[NTOK * D_MODEL], g_ql[NTOK * D_MODEL];
__device__ bf16  g_kh[NTOK * D_MODEL], g_kl[NTOK * D_MODEL];
__device__ bf16  g_vh[NTOK * D_MODEL], g_vl[NTOK * D_MODEL];
__device__ bf16  g_ch[NTOK * D_MODEL], g_cl[NTOK * D_MODEL];
__device__ float g_x1[NTOK * D_MODEL];
__device__ bf16  g_fh[NTOK * FF_DIM],  g_fl[NTOK * FF_DIM];
__device__ bf16  g_wqh[D_MODEL*D_MODEL], g_wql[D_MODEL*D_MODEL];
__device__ bf16  g_wkh[D_MODEL*D_MODEL], g_wkl[D_MODEL*D_MODEL];
__device__ bf16  g_wvh[D_MODEL*D_MODEL], g_wvl[D_MODEL*D_MODEL];
__device__ bf16  g_woh[D_MODEL*D_MODEL], g_wol[D_MODEL*D_MODEL];
__device__ bf16  g_w1h[D_MODEL*FF_DIM],  g_w1l[D_MODEL*FF_DIM];
__device__ bf16  g_w2h[FF_DIM*D_MODEL],  g_w2l[FF_DIM*D_MODEL];

// ---------------- PTX helpers ------------------------------------------------
__device__ __forceinline__ void split2(float v, bf16& h, bf16& l) {
    h = __float2bfloat16(v);
    l = __float2bfloat16(v - __bfloat162float(h));
}
__device__ __forceinline__ void ldsm_x4(uint32_t* r, uint32_t a) {
    asm volatile("ldmatrix.sync.aligned.m8n8.x4.shared.b16 {%0,%1,%2,%3},[%4];"
                 : "=r"(r[0]), "=r"(r[1]), "=r"(r[2]), "=r"(r[3]) : "r"(a));
}
__device__ __forceinline__ void ldsm_x4t(uint32_t* r, uint32_t a) {
    asm volatile("ldmatrix.sync.aligned.m8n8.x4.trans.shared.b16 {%0,%1,%2,%3},[%4];"
                 : "=r"(r[0]), "=r"(r[1]), "=r"(r[2]), "=r"(r[3]) : "r"(a));
}
__device__ __forceinline__ void mma16816(float* d, const uint32_t* a, const uint32_t* b) {
    asm volatile("mma.sync.aligned.m16n8k16.row.col.f32.bf16.bf16.f32 "
                 "{%0,%1,%2,%3},{%4,%5,%6,%7},{%8,%9},{%0,%1,%2,%3};"
                 : "+f"(d[0]), "+f"(d[1]), "+f"(d[2]), "+f"(d[3])
                 : "r"(a[0]), "r"(a[1]), "r"(a[2]), "r"(a[3]), "r"(b[0]), "r"(b[1]));
}
__device__ __forceinline__ void cp16(uint32_t s, const void* g) {
    asm volatile("cp.async.cg.shared.global [%0],[%1],16;" :: "r"(s), "l"(g));
}
__device__ __forceinline__ void cp_commit() { asm volatile("cp.async.commit_group;"); }
template<int N> __device__ __forceinline__ void cp_wait() {
    asm volatile("cp.async.wait_group %0;" :: "n"(N));
}

// ---------------- split (weights) -------------------------------------------
__global__ void split_kernel(const float* __restrict__ in,
                             bf16* __restrict__ hi, bf16* __restrict__ lo, int n4) {
    int i = blockIdx.x * 256 + threadIdx.x;
    if (i >= n4) return;
    float4 v = ((const float4*)in)[i];
    bf16 h0,h1,h2,h3,l0,l1,l2,l3;
    split2(v.x,h0,l0); split2(v.y,h1,l1); split2(v.z,h2,l2); split2(v.w,h3,l3);
    bf162 H0; H0.x=h0; H0.y=h1;  bf162 H1; H1.x=h2; H1.y=h3;
    bf162 L0; L0.x=l0; L0.y=l1;  bf162 L1; L1.x=l2; L1.y=l3;
    ((bf162*)hi)[i*2] = H0; ((bf162*)hi)[i*2+1] = H1;
    ((bf162*)lo)[i*2] = L0; ((bf162*)lo)[i*2+1] = L1;
}

// ---------------- LayerNorm -> bf16 hi/lo ------------------------------------
__global__ void ln_split_kernel(const float* __restrict__ x,
                                const float* __restrict__ g,
                                const float* __restrict__ b,
                                bf16* __restrict__ hi, bf16* __restrict__ lo) {
    int row = blockIdx.x;
    const float4* xr = (const float4*)(x + (size_t)row * D_MODEL);
    float4 v = xr[threadIdx.x];
    float sum   = v.x + v.y + v.z + v.w;
    float sumsq = v.x*v.x + v.y*v.y + v.z*v.z + v.w*v.w;
    #pragma unroll
    for (int o = 16; o > 0; o >>= 1) {
        sum   += __shfl_xor_sync(0xffffffffu, sum, o);
        sumsq += __shfl_xor_sync(0xffffffffu, sumsq, o);
    }
    __shared__ float s1[8], s2[8];
    int w = threadIdx.x >> 5, l = threadIdx.x & 31;
    if (l == 0) { s1[w] = sum; s2[w] = sumsq; }
    __syncthreads();
    float ts = 0.f, tq = 0.f;
    #pragma unroll
    for (int i = 0; i < 8; i++) { ts += s1[i]; tq += s2[i]; }
    float mu   = ts * (1.0f / D_MODEL);
    float var  = tq * (1.0f / D_MODEL) - mu * mu;
    float rstd = rsqrtf(var + EPSLN);
    float4 gv = ((const float4*)g)[threadIdx.x];
    float4 bv = ((const float4*)b)[threadIdx.x];
    float o0 = (v.x-mu)*rstd*gv.x + bv.x;
    float o1 = (v.y-mu)*rstd*gv.y + bv.y;
    float o2 = (v.z-mu)*rstd*gv.z + bv.z;
    float o3 = (v.w-mu)*rstd*gv.w + bv.w;
    bf16 h0,h1,h2,h3,l0,l1,l2,l3;
    split2(o0,h0,l0); split2(o1,h1,l1); split2(o2,h2,l2); split2(o3,h3,l3);
    size_t base2 = ((size_t)row * D_MODEL) / 2 + threadIdx.x * 2;
    bf162 H0; H0.x=h0; H0.y=h1;  bf162 H1; H1.x=h2; H1.y=h3;
    bf162 L0; L0.x=l0; L0.y=l1;  bf162 L1; L1.x=l2; L1.y=l3;
    ((bf162*)hi)[base2] = H0; ((bf162*)hi)[base2+1] = H1;
    ((bf162*)lo)[base2] = L0; ((bf162*)lo)[base2+1] = L1;
}

// ---------------- tensor-core GEMM (bf16x3 split) ----------------------------
#define BMT 128
#define BNT 128
#define BKT 32
#define ASTR 48
#define BSTR 136
#define SA_BYTES (BMT * ASTR * 2)
#define SB_BYTES (BKT * BSTR * 2)
#define STAGE_BYTES (2*SA_BYTES + 2*SB_BYTES)
#define GEMM_SMEM (2 * STAGE_BYTES)

template<int RELU, int RES, int EMITF, int EMITS>
__global__ void __launch_bounds__(256)
gemm_tc(const bf16* __restrict__ Ah, const bf16* __restrict__ Al,
        const bf16* __restrict__ Bh, const bf16* __restrict__ Bl,
        const float* __restrict__ bias, const float* __restrict__ res,
        float* __restrict__ C, bf16* __restrict__ Chi, bf16* __restrict__ Clo,
        int M, int N, int K) {
    extern __shared__ char smr[];
    uint32_t sbase = (uint32_t)__cvta_generic_to_shared(smr);
    int tid = threadIdx.x, lane = tid & 31, warp = tid >> 5;
    int wm = warp >> 1, wn = warp & 1;
    int bm = blockIdx.y, bn = blockIdx.x;
    size_t arow0 = (size_t)bm * BMT;
    int ncol0 = bn * BNT;

    float d[2][8][4];
    #pragma unroll
    for (int i = 0; i < 2; i++)
        #pragma unroll
        for (int j = 0; j < 8; j++)
            #pragma unroll
            for (int q = 0; q < 4; q++) d[i][j][q] = 0.f;

    auto load_stage = [&](int st, int k0) {
        uint32_t s = sbase + st * STAGE_BYTES;
        #pragma unroll
        for (int i = 0; i < 2; i++) {
            int slot = tid + i * 256;
            int r = slot >> 2, q = slot & 3;
            size_t go = (arow0 + r) * K + k0 + q * 8;
            uint32_t so = (uint32_t)(r * ASTR + q * 8) * 2;
            cp16(s + so, Ah + go);
            cp16(s + SA_BYTES + so, Al + go);
        }
        #pragma unroll
        for (int i = 0; i < 2; i++) {
            int slot = tid + i * 256;
            int r = slot >> 4, sg = slot & 15;
            size_t go = (size_t)(k0 + r) * N + ncol0 + sg * 8;
            uint32_t so = (uint32_t)(r * BSTR + sg * 8) * 2;
            cp16(s + 2*SA_BYTES + so, Bh + go);
            cp16(s + 2*SA_BYTES + SB_BYTES + so, Bl + go);
        }
        cp_commit();
    };

    int nK = K / BKT;
    load_stage(0, 0);
    int lr = lane & 15, lc = lane >> 4;

    for (int kt = 0; kt < nK; kt++) {
        if (kt + 1 < nK) { load_stage((kt + 1) & 1, (kt + 1) * BKT); cp_wait<1>(); }
        else             { cp_wait<0>(); }
        __syncthreads();
        uint32_t s   = sbase + (kt & 1) * STAGE_BYTES;
        uint32_t sAh = s, sAl = s + SA_BYTES;
        uint32_t sBh = s + 2*SA_BYTES, sBl = sBh + SB_BYTES;
        #pragma unroll
        for (int ks = 0; ks < BKT; ks += 16) {
            uint32_t fAh[2][4], fAl[2][4];
            #pragma unroll
            for (int mt = 0; mt < 2; mt++) {
                int row = wm * 32 + mt * 16 + lr;
                int col = ks + lc * 8;
                uint32_t off = (uint32_t)(row * ASTR + col) * 2;
                ldsm_x4(fAh[mt], sAh + off);
                ldsm_x4(fAl[mt], sAl + off);
            }
            #pragma unroll
            for (int np = 0; np < 4; np++) {
                int nb = wn * 64 + np * 16;
                uint32_t off = (uint32_t)((ks + lr) * BSTR + nb + lc * 8) * 2;
                uint32_t bh[4], bl[4];
                ldsm_x4t(bh, sBh + off);
                ldsm_x4t(bl, sBl + off);
                #pragma unroll
                for (int mt = 0; mt < 2; mt++) {
                    #pragma unroll
                    for (int nt = 0; nt < 2; nt++) {
                        float* dd = d[mt][np * 2 + nt];
                        mma16816(dd, fAh[mt], &bh[nt * 2]);
                        mma16816(dd, fAl[mt], &bh[nt * 2]);
                        mma16816(dd, fAh[mt], &bl[nt * 2]);
                    }
                }
            }
        }
        __syncthreads();
    }

    int g = lane >> 2, t = lane & 3;
    #pragma unroll
    for (int mt = 0; mt < 2; mt++) {
        #pragma unroll
        for (int nt = 0; nt < 8; nt++) {
            int col = ncol0 + wn * 64 + nt * 8 + t * 2;
            float b0 = bias[col], b1 = bias[col + 1];
            #pragma unroll
            for (int hh = 0; hh < 2; hh++) {
                int row = bm * BMT + wm * 32 + mt * 16 + g + hh * 8;
                float v0 = d[mt][nt][hh * 2 + 0] + b0;
                float v1 = d[mt][nt][hh * 2 + 1] + b1;
                if (RES) {
                    float2 rv = *(const float2*)(res + (size_t)row * N + col);
                    v0 += rv.x; v1 += rv.y;
                }
                if (RELU) { v0 = fmaxf(v0, 0.f); v1 = fmaxf(v1, 0.f); }
                if (EMITF)
                    *(float2*)(C + (size_t)row * N + col) = make_float2(v0, v1);
                if (EMITS) {
                    bf16 h0, l0, h1, l1;
                    split2(v0, h0, l0); split2(v1, h1, l1);
                    bf162 H; H.x = h0; H.y = h1;
                    bf162 L; L.x = l0; L.y = l1;
                    *(bf162*)(Chi + (size_t)row * N + col) = H;
                    *(bf162*)(Clo + (size_t)row * N + col) = L;
                }
            }
        }
    }
}

// ---------------- tensor-core flash attention --------------------------------
// 64x64 tiles, 8 warps (4 row-groups x 2 col-groups), bf16 hi/lo 3-term MMAs.
#define SSTR_B 144                    // bytes per 64-halft row (+8 pad)
#define TILE_B (64 * SSTR_B)          // 9216
#define OFF_QH 0
#define OFF_QL TILE_B
#define OFF_KV (2 * TILE_B)           // stages: Kh,Kl,Vh,Vl per stage
#define STG_B  (4 * TILE_B)           // 36864
#define OFF_PH (OFF_KV + 2 * STG_B)   // 92160
#define OFF_PL (OFF_PH + TILE_B)
#define OFF_ROWM (OFF_PL + TILE_B)    // float[64]
#define OFF_ROWL (OFF_ROWM + 256)
#define OFF_REDM (OFF_ROWL + 256)     // float[2][64]
#define OFF_REDS (OFF_REDM + 512)
#define OFF_MSK  (OFF_REDS + 512)     // int[2][64]
#define FLASH_SMEM (OFF_MSK + 512)    // 112640

__global__ void __launch_bounds__(256)
flash_tc(const bf16* __restrict__ Qh, const bf16* __restrict__ Ql,
         const bf16* __restrict__ Kh, const bf16* __restrict__ Kl,
         const bf16* __restrict__ Vh, const bf16* __restrict__ Vl,
         const int*  __restrict__ mask,
         bf16* __restrict__ Ohi, bf16* __restrict__ Olo) {
    extern __shared__ char smr[];
    uint32_t sb = (uint32_t)__cvta_generic_to_shared(smr);
    float* rowm = (float*)(smr + OFF_ROWM);
    float* rowl = (float*)(smr + OFF_ROWL);
    float* redm = (float*)(smr + OFF_REDM);
    float* reds = (float*)(smr + OFF_REDS);

    int tid = threadIdx.x, lane = tid & 31, warp = tid >> 5;
    int wm = warp >> 1, wn = warp & 1;
    int g = lane >> 2, t = lane & 3;
    int lr = lane & 15, lc = lane >> 4;
    int bh = blockIdx.y;
    int b = bh >> 4, h = bh & 15;
    int q0 = blockIdx.x * 64;

    size_t qg  = ((size_t)(b * SEQ + q0)) * D_MODEL + h * DHEAD;
    size_t kvg = ((size_t)(b * SEQ)) * D_MODEL + h * DHEAD;

    // Q tile loads (hi/lo)
    #pragma unroll
    for (int i = 0; i < 2; i++) {
        int slot = tid + i * 256;
        int r = slot >> 3, c8 = (slot & 7) * 8;
        uint32_t so = (uint32_t)r * SSTR_B + c8 * 2;
        cp16(sb + OFF_QH + so, Qh + qg + (size_t)r * D_MODEL + c8);
        cp16(sb + OFF_QL + so, Ql + qg + (size_t)r * D_MODEL + c8);
    }
    auto load_kv = [&](int st, int kv0) {
        uint32_t sK = sb + OFF_KV + st * STG_B;
        #pragma unroll
        for (int i = 0; i < 2; i++) {
            int slot = tid + i * 256;
            int r = slot >> 3, c8 = (slot & 7) * 8;
            size_t go = kvg + (size_t)(kv0 + r) * D_MODEL + c8;
            uint32_t so = (uint32_t)r * SSTR_B + c8 * 2;
            cp16(sK + so,              Kh + go);
            cp16(sK + TILE_B + so,     Kl + go);
            cp16(sK + 2*TILE_B + so,   Vh + go);
            cp16(sK + 3*TILE_B + so,   Vl + go);
        }
        if (tid < 16)
            cp16(sb + OFF_MSK + st * 256 + tid * 16, mask + b * SEQ + kv0 + tid * 4);
    };
    load_kv(0, 0);
    cp_commit();
    if (tid < 64) { rowm[tid] = -1e30f; rowl[tid] = 0.f; }

    float o[4][4];
    #pragma unroll
    for (int i = 0; i < 4; i++)
        #pragma unroll
        for (int j = 0; j < 4; j++) o[i][j] = 0.f;

    int rg = wm * 16 + g, rg8 = rg + 8;

    for (int kt = 0; kt < 32; kt++) {
        cp_wait<0>();
        __syncthreads();
        if (kt + 1 < 32) { load_kv((kt + 1) & 1, (kt + 1) * 64); cp_commit(); }

        uint32_t sK = sb + OFF_KV + (kt & 1) * STG_B;
        const int* mk = (const int*)(smr + OFF_MSK + (kt & 1) * 256);

        // ---- S = Q @ K^T (3-term) ----
        float s[4][4];
        #pragma unroll
        for (int j = 0; j < 4; j++)
            #pragma unroll
            for (int q = 0; q < 4; q++) s[j][q] = 0.f;
        #pragma unroll
        for (int ks = 0; ks < 4; ks++) {
            uint32_t qoff = (uint32_t)(wm * 16 + lr) * SSTR_B + (ks * 16 + lc * 8) * 2;
            uint32_t aQh[4], aQl[4];
            ldsm_x4(aQh, sb + OFF_QH + qoff);
            ldsm_x4(aQl, sb + OFF_QL + qoff);
            #pragma unroll
            for (int npair = 0; npair < 2; npair++) {
                uint32_t koff = (uint32_t)(wn * 32 + npair * 16 + lr) * SSTR_B + (ks * 16 + lc * 8) * 2;
                uint32_t bKh[4], bKl[4];
                ldsm_x4(bKh, sK + koff);
                ldsm_x4(bKl, sK + TILE_B + koff);
                uint32_t f0h[2] = {bKh[0], bKh[2]}, f1h[2] = {bKh[1], bKh[3]};
                uint32_t f0l[2] = {bKl[0], bKl[2]}, f1l[2] = {bKl[1], bKl[3]};
                float* s0 = s[npair * 2 + 0];
                float* s1 = s[npair * 2 + 1];
                mma16816(s0, aQh, f0h); mma16816(s0, aQl, f0h); mma16816(s0, aQh, f0l);
                mma16816(s1, aQh, f1h); mma16816(s1, aQl, f1h); mma16816(s1, aQh, f1l);
            }
        }
        // ---- mask + scale + row max ----
        float mg = -1e30f, mg8 = -1e30f;
        #pragma unroll
        for (int j = 0; j < 4; j++) {
            int c0 = wn * 32 + (j >> 1) * 16 + (j & 1) * 8 + t * 2;
            int m0 = mk[c0], m1 = mk[c0 + 1];
            s[j][0] = m0 ? s[j][0] * 0.125f : -1e30f;
            s[j][1] = m1 ? s[j][1] * 0.125f : -1e30f;
            s[j][2] = m0 ? s[j][2] * 0.125f : -1e30f;
            s[j][3] = m1 ? s[j][3] * 0.125f : -1e30f;
            mg  = fmaxf(mg,  fmaxf(s[j][0], s[j][1]));
            mg8 = fmaxf(mg8, fmaxf(s[j][2], s[j][3]));
        }
        #pragma unroll
        for (int off = 1; off <= 2; off <<= 1) {
            mg  = fmaxf(mg,  __shfl_xor_sync(0xffffffffu, mg,  off));
            mg8 = fmaxf(mg8, __shfl_xor_sync(0xffffffffu, mg8, off));
        }
        if (t == 0) { redm[wn * 64 + rg] = mg; redm[wn * 64 + rg8] = mg8; }
        __syncthreads();

        // ---- online softmax: exp, P hi/lo to smem, sums, O rescale ----
        float mo  = rowm[rg],  mo8 = rowm[rg8];
        float mn  = fmaxf(mo,  fmaxf(redm[rg],      redm[64 + rg]));
        float mn8 = fmaxf(mo8, fmaxf(redm[rg8],     redm[64 + rg8]));
        float al  = __expf(mo - mn), al8 = __expf(mo8 - mn8);
        float sg = 0.f, sg8 = 0.f;
        #pragma unroll
        for (int j = 0; j < 4; j++) {
            int c0 = wn * 32 + (j >> 1) * 16 + (j & 1) * 8 + t * 2;
            float p0 = __expf(s[j][0] - mn);
            float p1 = __expf(s[j][1] - mn);
            float p2 = __expf(s[j][2] - mn8);
            float p3 = __expf(s[j][3] - mn8);
            sg += p0 + p1; sg8 += p2 + p3;
            bf16 h0,l0,h1,l1,h2,l2,h3,l3;
            split2(p0,h0,l0); split2(p1,h1,l1); split2(p2,h2,l2); split2(p3,h3,l3);
            bf162 H01; H01.x=h0; H01.y=h1;  bf162 L01; L01.x=l0; L01.y=l1;
            bf162 H23; H23.x=h2; H23.y=h3;  bf162 L23; L23.x=l2; L23.y=l3;
            *(bf162*)(smr + OFF_PH + rg  * SSTR_B + c0 * 2) = H01;
            *(bf162*)(smr + OFF_PL + rg  * SSTR_B + c0 * 2) = L01;
            *(bf162*)(smr + OFF_PH + rg8 * SSTR_B + c0 * 2) = H23;
            *(bf162*)(smr + OFF_PL + rg8 * SSTR_B + c0 * 2) = L23;
        }
        #pragma unroll
        for (int off = 1; off <= 2; off <<= 1) {
            sg  += __shfl_xor_sync(0xffffffffu, sg,  off);
            sg8 += __shfl_xor_sync(0xffffffffu, sg8, off);
        }
        if (t == 0) { reds[wn * 64 + rg] = sg; reds[wn * 64 + rg8] = sg8; }
        #pragma unroll
        for (int j = 0; j < 4; j++) {
            o[j][0] *= al;  o[j][1] *= al;
            o[j][2] *= al8; o[j][3] *= al8;
        }
        __syncthreads();

        // ---- update running stats (one col-group of warps) ----
        if (wn == 0 && lane < 16) {
            int row = wm * 16 + lane;
            float mo_r = rowm[row];
            float mn_r = fmaxf(mo_r, fmaxf(redm[row], redm[64 + row]));
            rowm[row] = mn_r;
            rowl[row] = rowl[row] * __expf(mo_r - mn_r) + reds[row] + reds[64 + row];
        }

        // ---- O += P @ V (3-term) ----
        #pragma unroll
        for (int ks = 0; ks < 4; ks++) {
            uint32_t poff = (uint32_t)(wm * 16 + lr) * SSTR_B + (ks * 16 + lc * 8) * 2;
            uint32_t aPh[4], aPl[4];
            ldsm_x4(aPh, sb + OFF_PH + poff);
            ldsm_x4(aPl, sb + OFF_PL + poff);
            #pragma unroll
            for (int dp = 0; dp < 2; dp++) {
                uint32_t voff = (uint32_t)(ks * 16 + lr) * SSTR_B + (wn * 32 + dp * 16 + lc * 8) * 2;
                uint32_t bVh[4], bVl[4];
                ldsm_x4t(bVh, sK + 2*TILE_B + voff);
                ldsm_x4t(bVl, sK + 3*TILE_B + voff);
                #pragma unroll
                for (int db = 0; db < 2; db++) {
                    float* oo = o[dp * 2 + db];
                    mma16816(oo, aPh, &bVh[db * 2]);
                    mma16816(oo, aPl, &bVh[db * 2]);
                    mma16816(oo, aPh, &bVl[db * 2]);
                }
            }
        }
    }
    __syncthreads();

    // ---- epilogue: divide by l, split hi/lo, store ----
    float li  = 1.f / rowl[rg];
    float li8 = 1.f / rowl[rg8];
    size_t ob = ((size_t)(b * SEQ + q0)) * D_MODEL + h * DHEAD;
    #pragma unroll
    for (int j = 0; j < 4; j++) {
        int c0 = wn * 32 + (j >> 1) * 16 + (j & 1) * 8 + t * 2;
        float v0 = o[j][0] * li,  v1 = o[j][1] * li;
        float v2 = o[j][2] * li8, v3 = o[j][3] * li8;
        bf16 h0,l0,h1,l1,h2,l2,h3,l3;
        split2(v0,h0,l0); split2(v1,h1,l1); split2(v2,h2,l2); split2(v3,h3,l3);
        bf162 H01; H01.x=h0; H01.y=h1;  bf162 L01; L01.x=l0; L01.y=l1;
        bf162 H23; H23.x=h2; H23.y=h3;  bf162 L23; L23.x=l2; L23.y=l3;
        *(bf162*)(Ohi + ob + (size_t)rg  * D_MODEL + c0) = H01;
        *(bf162*)(Olo + ob + (size_t)rg  * D_MODEL + c0) = L01;
        *(bf162*)(Ohi + ob + (size_t)rg8 * D_MODEL + c0) = H23;
        *(bf162*)(Olo + ob + (size_t)rg8 * D_MODEL + c0) = L23;
    }
}

// ---------------- launch ------------------------------------------------------
extern "C" void kernel_launch(void* const* d_in, const int* in_sizes, int n_in,
                              void* d_out, int out_size) {
    const float* x    = (const float*)d_in[0];
    const int*   mask = (const int*)  d_in[1];
    const float* wq   = (const float*)d_in[2];
    const float* bq   = (const float*)d_in[3];
    const float* wk   = (const float*)d_in[4];
    const float* bk   = (const float*)d_in[5];
    const float* wv   = (const float*)d_in[6];
    const float* bv   = (const float*)d_in[7];
    const float* wo   = (const float*)d_in[8];
    const float* bo   = (const float*)d_in[9];
    const float* ln1g = (const float*)d_in[10];
    const float* ln1b = (const float*)d_in[11];
    const float* ln2g = (const float*)d_in[12];
    const float* ln2b = (const float*)d_in[13];
    const float* w1   = (const float*)d_in[14];
    const float* b1   = (const float*)d_in[15];
    const float* w2   = (const float*)d_in[16];
    const float* b2   = (const float*)d_in[17];
    float* out = (float*)d_out;

    bf16 *hh, *hl, *qh, *ql, *kh, *kl, *vh, *vl, *ch, *cl, *fh, *fl;
    bf16 *wqh, *wql, *wkh, *wkl, *wvh, *wvl, *woh, *wol, *w1h, *w1l, *w2h, *w2l;
    float *px1;
    cudaGetSymbolAddress((void**)&hh, g_hh);   cudaGetSymbolAddress((void**)&hl, g_hl);
    cudaGetSymbolAddress((void**)&qh, g_qh);   cudaGetSymbolAddress((void**)&ql, g_ql);
    cudaGetSymbolAddress((void**)&kh, g_kh);   cudaGetSymbolAddress((void**)&kl, g_kl);
    cudaGetSymbolAddress((void**)&vh, g_vh);   cudaGetSymbolAddress((void**)&vl, g_vl);
    cudaGetSymbolAddress((void**)&ch, g_ch);   cudaGetSymbolAddress((void**)&cl, g_cl);
    cudaGetSymbolAddress((void**)&fh, g_fh);   cudaGetSymbolAddress((void**)&fl, g_fl);
    cudaGetSymbolAddress((void**)&wqh, g_wqh); cudaGetSymbolAddress((void**)&wql, g_wql);
    cudaGetSymbolAddress((void**)&wkh, g_wkh); cudaGetSymbolAddress((void**)&wkl, g_wkl);
    cudaGetSymbolAddress((void**)&wvh, g_wvh); cudaGetSymbolAddress((void**)&wvl, g_wvl);
    cudaGetSymbolAddress((void**)&woh, g_woh); cudaGetSymbolAddress((void**)&wol, g_wol);
    cudaGetSymbolAddress((void**)&w1h, g_w1h); cudaGetSymbolAddress((void**)&w1l, g_w1l);
    cudaGetSymbolAddress((void**)&w2h, g_w2h); cudaGetSymbolAddress((void**)&w2l, g_w2l);
    cudaGetSymbolAddress((void**)&px1, g_x1);

    cudaFuncSetAttribute(gemm_tc<0,0,0,1>, cudaFuncAttributeMaxDynamicSharedMemorySize, GEMM_SMEM);
    cudaFuncSetAttribute(gemm_tc<0,1,1,0>, cudaFuncAttributeMaxDynamicSharedMemorySize, GEMM_SMEM);
    cudaFuncSetAttribute(gemm_tc<1,0,0,1>, cudaFuncAttributeMaxDynamicSharedMemorySize, GEMM_SMEM);
    cudaFuncSetAttribute(flash_tc, cudaFuncAttributeMaxDynamicSharedMemorySize, FLASH_SMEM);

    int n1m4 = D_MODEL * D_MODEL / 4, n4m4 = D_MODEL * FF_DIM / 4;
    split_kernel<<<(n1m4 + 255) / 256, 256>>>(wq, wqh, wql, n1m4);
    split_kernel<<<(n1m4 + 255) / 256, 256>>>(wk, wkh, wkl, n1m4);
    split_kernel<<<(n1m4 + 255) / 256, 256>>>(wv, wvh, wvl, n1m4);
    split_kernel<<<(n1m4 + 255) / 256, 256>>>(wo, woh, wol, n1m4);
    split_kernel<<<(n4m4 + 255) / 256, 256>>>(w1, w1h, w1l, n4m4);
    split_kernel<<<(n4m4 + 255) / 256, 256>>>(w2, w2h, w2l, n4m4);

    // LN1 -> h hi/lo
    ln_split_kernel<<<NTOK, 256>>>(x, ln1g, ln1b, hh, hl);

    // QKV projections -> bf16 hi/lo
    dim3 gqkv(D_MODEL / BNT, NTOK / BMT);
    gemm_tc<0,0,0,1><<<gqkv, 256, GEMM_SMEM>>>(hh, hl, wqh, wql, bq, nullptr,
                                               nullptr, qh, ql, NTOK, D_MODEL, D_MODEL);
    gemm_tc<0,0,0,1><<<gqkv, 256, GEMM_SMEM>>>(hh, hl, wkh, wkl, bk, nullptr,
                                               nullptr, kh, kl, NTOK, D_MODEL, D_MODEL);
    gemm_tc<0,0,0,1><<<gqkv, 256, GEMM_SMEM>>>(hh, hl, wvh, wvl, bv, nullptr,
                                               nullptr, vh, vl, NTOK, D_MODEL, D_MODEL);

    // attention (tensor cores) -> ctx hi/lo
    dim3 gfa(SEQ / 64, 2 * NHEADS);
    flash_tc<<<gfa, 256, FLASH_SMEM>>>(qh, ql, kh, kl, vh, vl, mask, ch, cl);

    // O projection + residual 1 -> x1 fp32
    gemm_tc<0,1,1,0><<<gqkv, 256, GEMM_SMEM>>>(ch, cl, woh, wol, bo, x,
                                               px1, nullptr, nullptr, NTOK, D_MODEL, D_MODEL);

    // LN2 -> h hi/lo
    ln_split_kernel<<<NTOK, 256>>>(px1, ln2g, ln2b, hh, hl);

    // FF1 (relu) -> ff hi/lo
    dim3 gff1(FF_DIM / BNT, NTOK / BMT);
    gemm_tc<1,0,0,1><<<gff1, 256, GEMM_SMEM>>>(hh, hl, w1h, w1l, b1, nullptr,
                                               nullptr, fh, fl, NTOK, FF_DIM, D_MODEL);

    // FF2 + residual 2 -> out
    dim3 gff2(D_MODEL / BNT, NTOK / BMT);
    gemm_tc<0,1,1,0><<<gff2, 256, GEMM_SMEM>>>(fh, fl, w2h, w2l, b2, px1,
                                               out, nullptr, nullptr, NTOK, D_MODEL, FF_DIM);
}

// round 6
// speedup vs baseline: 4.0076x; 1.3300x over previous
#include <cuda_runtime.h>
#include <cuda_fp16.h>
#include <math.h>
#include <stdint.h>

#define D_MODEL 1024
#define FF_DIM  4096
#define NTOK    4096
#define SEQ     2048
#define NHEADS  16
#define DHEAD   64
#define EPSLN   1e-5f

typedef __half  f16;
typedef __half2 f162;

// ---------------- scratch ----------------------------------------------------
__device__ f16  g_hh[NTOK * D_MODEL], g_hl[NTOK * D_MODEL];
__device__ f16  g_qh[NTOK * D_MODEL], g_ql[NTOK * D_MODEL];
__device__ f16  g_kh[NTOK * D_MODEL];
__device__ f16  g_vh[NTOK * D_MODEL];
__device__ f16  g_ch[NTOK * D_MODEL], g_cl[NTOK * D_MODEL];
__device__ float g_x1[NTOK * D_MODEL];
__device__ f16  g_fh[NTOK * FF_DIM],  g_fl[NTOK * FF_DIM];
__device__ f16  g_wq[D_MODEL*D_MODEL], g_wk[D_MODEL*D_MODEL];
__device__ f16  g_wv[D_MODEL*D_MODEL], g_wo[D_MODEL*D_MODEL];
__device__ f16  g_w1[D_MODEL*FF_DIM],  g_w2[FF_DIM*D_MODEL];

// ---------------- PTX helpers ------------------------------------------------
__device__ __forceinline__ void split2h(float v, f16& h, f16& l) {
    h = __float2half_rn(v);
    l = __float2half_rn(v - __half2float(h));
}
__device__ __forceinline__ void ldsm_x4(uint32_t* r, uint32_t a) {
    asm volatile("ldmatrix.sync.aligned.m8n8.x4.shared.b16 {%0,%1,%2,%3},[%4];"
                 : "=r"(r[0]), "=r"(r[1]), "=r"(r[2]), "=r"(r[3]) : "r"(a));
}
__device__ __forceinline__ void ldsm_x4t(uint32_t* r, uint32_t a) {
    asm volatile("ldmatrix.sync.aligned.m8n8.x4.trans.shared.b16 {%0,%1,%2,%3},[%4];"
                 : "=r"(r[0]), "=r"(r[1]), "=r"(r[2]), "=r"(r[3]) : "r"(a));
}
__device__ __forceinline__ void mma16816(float* d, const uint32_t* a, const uint32_t* b) {
    asm volatile("mma.sync.aligned.m16n8k16.row.col.f32.f16.f16.f32 "
                 "{%0,%1,%2,%3},{%4,%5,%6,%7},{%8,%9},{%0,%1,%2,%3};"
                 : "+f"(d[0]), "+f"(d[1]), "+f"(d[2]), "+f"(d[3])
                 : "r"(a[0]), "r"(a[1]), "r"(a[2]), "r"(a[3]), "r"(b[0]), "r"(b[1]));
}
__device__ __forceinline__ void cp16(uint32_t s, const void* g) {
    asm volatile("cp.async.cg.shared.global [%0],[%1],16;" :: "r"(s), "l"(g));
}
__device__ __forceinline__ void cp_commit() { asm volatile("cp.async.commit_group;"); }
template<int N> __device__ __forceinline__ void cp_wait() {
    asm volatile("cp.async.wait_group %0;" :: "n"(N));
}

// ---------------- weight convert (fp32 -> fp16 hi) ---------------------------
__global__ void cvt_kernel(const float* __restrict__ in, f16* __restrict__ hi, int n4) {
    int i = blockIdx.x * 256 + threadIdx.x;
    if (i >= n4) return;
    float4 v = ((const float4*)in)[i];
    ((f162*)hi)[i*2]   = __floats2half2_rn(v.x, v.y);
    ((f162*)hi)[i*2+1] = __floats2half2_rn(v.z, v.w);
}

// ---------------- LayerNorm -> fp16 hi/lo ------------------------------------
__global__ void ln_split_kernel(const float* __restrict__ x,
                                const float* __restrict__ g,
                                const float* __restrict__ b,
                                f16* __restrict__ hi, f16* __restrict__ lo) {
    int row = blockIdx.x;
    const float4* xr = (const float4*)(x + (size_t)row * D_MODEL);
    float4 v = xr[threadIdx.x];
    float sum   = v.x + v.y + v.z + v.w;
    float sumsq = v.x*v.x + v.y*v.y + v.z*v.z + v.w*v.w;
    #pragma unroll
    for (int o = 16; o > 0; o >>= 1) {
        sum   += __shfl_xor_sync(0xffffffffu, sum, o);
        sumsq += __shfl_xor_sync(0xffffffffu, sumsq, o);
    }
    __shared__ float s1[8], s2[8];
    int w = threadIdx.x >> 5, l = threadIdx.x & 31;
    if (l == 0) { s1[w] = sum; s2[w] = sumsq; }
    __syncthreads();
    float ts = 0.f, tq = 0.f;
    #pragma unroll
    for (int i = 0; i < 8; i++) { ts += s1[i]; tq += s2[i]; }
    float mu   = ts * (1.0f / D_MODEL);
    float var  = tq * (1.0f / D_MODEL) - mu * mu;
    float rstd = rsqrtf(var + EPSLN);
    float4 gv = ((const float4*)g)[threadIdx.x];
    float4 bv = ((const float4*)b)[threadIdx.x];
    float o0 = (v.x-mu)*rstd*gv.x + bv.x;
    float o1 = (v.y-mu)*rstd*gv.y + bv.y;
    float o2 = (v.z-mu)*rstd*gv.z + bv.z;
    float o3 = (v.w-mu)*rstd*gv.w + bv.w;
    f16 h0,h1,h2,h3,l0,l1,l2,l3;
    split2h(o0,h0,l0); split2h(o1,h1,l1); split2h(o2,h2,l2); split2h(o3,h3,l3);
    size_t base2 = ((size_t)row * D_MODEL) / 2 + threadIdx.x * 2;
    ((f162*)hi)[base2]   = __halves2half2(h0, h1);
    ((f162*)hi)[base2+1] = __halves2half2(h2, h3);
    ((f162*)lo)[base2]   = __halves2half2(l0, l1);
    ((f162*)lo)[base2+1] = __halves2half2(l2, l3);
}

// ---------------- tensor-core GEMM (fp16 2-term) -----------------------------
// C = (Ah+Al) @ Bh (+bias)(+res)(relu). A hi/lo [M,K], B hi [K,N] row-major.
#define BMT 128
#define BNT 128
#define BKT 32
#define ASTR 40          // halves per A row in smem (80B, ldsm conflict-free)
#define BSTR 136         // halves per B row in smem (272B, conflict-free)
#define SA_BYTES (BMT * ASTR * 2)                 // 10240
#define SB_BYTES (BKT * BSTR * 2)                 // 8704
#define STAGE_BYTES (2*SA_BYTES + SB_BYTES)       // 29184
#define GEMM_SMEM (2 * STAGE_BYTES)               // 58368

template<int RELU, int RES, int EMITF, int EMITS, int EMITLO>
__global__ void __launch_bounds__(256)
gemm_tc(const f16* __restrict__ Ah, const f16* __restrict__ Al,
        const f16* __restrict__ Bh,
        const float* __restrict__ bias, const float* __restrict__ res,
        float* __restrict__ C, f16* __restrict__ Chi, f16* __restrict__ Clo,
        int M, int N, int K) {
    extern __shared__ char smr[];
    uint32_t sbase = (uint32_t)__cvta_generic_to_shared(smr);
    int tid = threadIdx.x, lane = tid & 31, warp = tid >> 5;
    int wm = warp >> 1, wn = warp & 1;
    int bm = blockIdx.y, bn = blockIdx.x;
    size_t arow0 = (size_t)bm * BMT;
    int ncol0 = bn * BNT;

    float d[2][8][4];
    #pragma unroll
    for (int i = 0; i < 2; i++)
        #pragma unroll
        for (int j = 0; j < 8; j++)
            #pragma unroll
            for (int q = 0; q < 4; q++) d[i][j][q] = 0.f;

    auto load_stage = [&](int st, int k0) {
        uint32_t s = sbase + st * STAGE_BYTES;
        #pragma unroll
        for (int i = 0; i < 2; i++) {
            int slot = tid + i * 256;
            int r = slot >> 2, q = slot & 3;
            size_t go = (arow0 + r) * K + k0 + q * 8;
            uint32_t so = (uint32_t)(r * ASTR + q * 8) * 2;
            cp16(s + so, Ah + go);
            cp16(s + SA_BYTES + so, Al + go);
        }
        #pragma unroll
        for (int i = 0; i < 2; i++) {
            int slot = tid + i * 256;
            int r = slot >> 4, sg = slot & 15;
            size_t go = (size_t)(k0 + r) * N + ncol0 + sg * 8;
            uint32_t so = (uint32_t)(r * BSTR + sg * 8) * 2;
            cp16(s + 2*SA_BYTES + so, Bh + go);
        }
        cp_commit();
    };

    int nK = K / BKT;
    load_stage(0, 0);
    int lr = lane & 15, lc = lane >> 4;

    for (int kt = 0; kt < nK; kt++) {
        if (kt + 1 < nK) { load_stage((kt + 1) & 1, (kt + 1) * BKT); cp_wait<1>(); }
        else             { cp_wait<0>(); }
        __syncthreads();
        uint32_t s   = sbase + (kt & 1) * STAGE_BYTES;
        uint32_t sAh = s, sAl = s + SA_BYTES;
        uint32_t sBh = s + 2*SA_BYTES;
        #pragma unroll
        for (int ks = 0; ks < BKT; ks += 16) {
            uint32_t fAh[2][4], fAl[2][4];
            #pragma unroll
            for (int mt = 0; mt < 2; mt++) {
                int row = wm * 32 + mt * 16 + lr;
                int col = ks + lc * 8;
                uint32_t off = (uint32_t)(row * ASTR + col) * 2;
                ldsm_x4(fAh[mt], sAh + off);
                ldsm_x4(fAl[mt], sAl + off);
            }
            #pragma unroll
            for (int np = 0; np < 4; np++) {
                int nb = wn * 64 + np * 16;
                uint32_t off = (uint32_t)((ks + lr) * BSTR + nb + lc * 8) * 2;
                uint32_t bh[4];
                ldsm_x4t(bh, sBh + off);
                #pragma unroll
                for (int mt = 0; mt < 2; mt++) {
                    #pragma unroll
                    for (int nt = 0; nt < 2; nt++) {
                        float* dd = d[mt][np * 2 + nt];
                        mma16816(dd, fAh[mt], &bh[nt * 2]);
                        mma16816(dd, fAl[mt], &bh[nt * 2]);
                    }
                }
            }
        }
        __syncthreads();
    }

    int g = lane >> 2, t = lane & 3;
    #pragma unroll
    for (int mt = 0; mt < 2; mt++) {
        #pragma unroll
        for (int nt = 0; nt < 8; nt++) {
            int col = ncol0 + wn * 64 + nt * 8 + t * 2;
            float b0 = bias[col], b1 = bias[col + 1];
            #pragma unroll
            for (int hh = 0; hh < 2; hh++) {
                int row = bm * BMT + wm * 32 + mt * 16 + g + hh * 8;
                float v0 = d[mt][nt][hh * 2 + 0] + b0;
                float v1 = d[mt][nt][hh * 2 + 1] + b1;
                if (RES) {
                    float2 rv = *(const float2*)(res + (size_t)row * N + col);
                    v0 += rv.x; v1 += rv.y;
                }
                if (RELU) { v0 = fmaxf(v0, 0.f); v1 = fmaxf(v1, 0.f); }
                if (EMITF)
                    *(float2*)(C + (size_t)row * N + col) = make_float2(v0, v1);
                if (EMITS) {
                    f16 h0, l0, h1, l1;
                    split2h(v0, h0, l0); split2h(v1, h1, l1);
                    *(f162*)(Chi + (size_t)row * N + col) = __halves2half2(h0, h1);
                    if (EMITLO)
                        *(f162*)(Clo + (size_t)row * N + col) = __halves2half2(l0, l1);
                }
            }
        }
    }
}

// ---------------- tensor-core flash attention (fp16 2-term) ------------------
#define SSTR_B 144                    // bytes per 64-half row (+16 pad)
#define TILE_B (64 * SSTR_B)          // 9216
#define OFF_QH 0
#define OFF_QL TILE_B
#define OFF_KV (2 * TILE_B)           // per stage: Kh, Vh
#define STG_B  (2 * TILE_B)           // 18432
#define OFF_PH (OFF_KV + 2 * STG_B)   // 55296
#define OFF_PL (OFF_PH + TILE_B)      // 64512
#define OFF_ROWM (OFF_PL + TILE_B)    // 73728 float[64]
#define OFF_ROWL (OFF_ROWM + 256)
#define OFF_REDM (OFF_ROWL + 256)     // float[2][64]
#define OFF_REDS (OFF_REDM + 512)
#define OFF_MSK  (OFF_REDS + 512)     // int[2][64]
#define FLASH_SMEM (OFF_MSK + 512)    // 75776

__global__ void __launch_bounds__(256)
flash_tc(const f16* __restrict__ Qh, const f16* __restrict__ Ql,
         const f16* __restrict__ Kh, const f16* __restrict__ Vh,
         const int*  __restrict__ mask,
         f16* __restrict__ Ohi, f16* __restrict__ Olo) {
    extern __shared__ char smr[];
    uint32_t sb = (uint32_t)__cvta_generic_to_shared(smr);
    float* rowm = (float*)(smr + OFF_ROWM);
    float* rowl = (float*)(smr + OFF_ROWL);
    float* redm = (float*)(smr + OFF_REDM);
    float* reds = (float*)(smr + OFF_REDS);

    int tid = threadIdx.x, lane = tid & 31, warp = tid >> 5;
    int wm = warp >> 1, wn = warp & 1;
    int g = lane >> 2, t = lane & 3;
    int lr = lane & 15, lc = lane >> 4;
    int bh = blockIdx.y;
    int b = bh >> 4, h = bh & 15;
    int q0 = blockIdx.x * 64;

    size_t qg  = ((size_t)(b * SEQ + q0)) * D_MODEL + h * DHEAD;
    size_t kvg = ((size_t)(b * SEQ)) * D_MODEL + h * DHEAD;

    #pragma unroll
    for (int i = 0; i < 2; i++) {
        int slot = tid + i * 256;
        int r = slot >> 3, c8 = (slot & 7) * 8;
        uint32_t so = (uint32_t)r * SSTR_B + c8 * 2;
        cp16(sb + OFF_QH + so, Qh + qg + (size_t)r * D_MODEL + c8);
        cp16(sb + OFF_QL + so, Ql + qg + (size_t)r * D_MODEL + c8);
    }
    auto load_kv = [&](int st, int kv0) {
        uint32_t sK = sb + OFF_KV + st * STG_B;
        #pragma unroll
        for (int i = 0; i < 2; i++) {
            int slot = tid + i * 256;
            int r = slot >> 3, c8 = (slot & 7) * 8;
            size_t go = kvg + (size_t)(kv0 + r) * D_MODEL + c8;
            uint32_t so = (uint32_t)r * SSTR_B + c8 * 2;
            cp16(sK + so,          Kh + go);
            cp16(sK + TILE_B + so, Vh + go);
        }
        if (tid < 16)
            cp16(sb + OFF_MSK + st * 256 + tid * 16, mask + b * SEQ + kv0 + tid * 4);
    };
    load_kv(0, 0);
    cp_commit();
    if (tid < 64) { rowm[tid] = -1e30f; rowl[tid] = 0.f; }

    float o[4][4];
    #pragma unroll
    for (int i = 0; i < 4; i++)
        #pragma unroll
        for (int j = 0; j < 4; j++) o[i][j] = 0.f;

    int rg = wm * 16 + g, rg8 = rg + 8;

    for (int kt = 0; kt < 32; kt++) {
        cp_wait<0>();
        __syncthreads();
        if (kt + 1 < 32) { load_kv((kt + 1) & 1, (kt + 1) * 64); cp_commit(); }

        uint32_t sK = sb + OFF_KV + (kt & 1) * STG_B;
        const int* mk = (const int*)(smr + OFF_MSK + (kt & 1) * 256);

        // ---- S = Q @ K^T (2-term fp16) ----
        float s[4][4];
        #pragma unroll
        for (int j = 0; j < 4; j++)
            #pragma unroll
            for (int q = 0; q < 4; q++) s[j][q] = 0.f;
        #pragma unroll
        for (int ks = 0; ks < 4; ks++) {
            uint32_t qoff = (uint32_t)(wm * 16 + lr) * SSTR_B + (ks * 16 + lc * 8) * 2;
            uint32_t aQh[4], aQl[4];
            ldsm_x4(aQh, sb + OFF_QH + qoff);
            ldsm_x4(aQl, sb + OFF_QL + qoff);
            #pragma unroll
            for (int npair = 0; npair < 2; npair++) {
                uint32_t koff = (uint32_t)(wn * 32 + npair * 16 + lr) * SSTR_B + (ks * 16 + lc * 8) * 2;
                uint32_t bKh[4];
                ldsm_x4(bKh, sK + koff);
                uint32_t f0h[2] = {bKh[0], bKh[2]}, f1h[2] = {bKh[1], bKh[3]};
                float* s0 = s[npair * 2 + 0];
                float* s1 = s[npair * 2 + 1];
                mma16816(s0, aQh, f0h); mma16816(s0, aQl, f0h);
                mma16816(s1, aQh, f1h); mma16816(s1, aQl, f1h);
            }
        }
        // ---- mask + scale + row max ----
        float mg = -1e30f, mg8 = -1e30f;
        #pragma unroll
        for (int j = 0; j < 4; j++) {
            int c0 = wn * 32 + (j >> 1) * 16 + (j & 1) * 8 + t * 2;
            int m0 = mk[c0], m1 = mk[c0 + 1];
            s[j][0] = m0 ? s[j][0] * 0.125f : -1e30f;
            s[j][1] = m1 ? s[j][1] * 0.125f : -1e30f;
            s[j][2] = m0 ? s[j][2] * 0.125f : -1e30f;
            s[j][3] = m1 ? s[j][3] * 0.125f : -1e30f;
            mg  = fmaxf(mg,  fmaxf(s[j][0], s[j][1]));
            mg8 = fmaxf(mg8, fmaxf(s[j][2], s[j][3]));
        }
        #pragma unroll
        for (int off = 1; off <= 2; off <<= 1) {
            mg  = fmaxf(mg,  __shfl_xor_sync(0xffffffffu, mg,  off));
            mg8 = fmaxf(mg8, __shfl_xor_sync(0xffffffffu, mg8, off));
        }
        if (t == 0) { redm[wn * 64 + rg] = mg; redm[wn * 64 + rg8] = mg8; }
        __syncthreads();

        // ---- online softmax ----
        float mo  = rowm[rg],  mo8 = rowm[rg8];
        float mn  = fmaxf(mo,  fmaxf(redm[rg],  redm[64 + rg]));
        float mn8 = fmaxf(mo8, fmaxf(redm[rg8], redm[64 + rg8]));
        float al  = __expf(mo - mn), al8 = __expf(mo8 - mn8);
        float sg = 0.f, sg8 = 0.f;
        #pragma unroll
        for (int j = 0; j < 4; j++) {
            int c0 = wn * 32 + (j >> 1) * 16 + (j & 1) * 8 + t * 2;
            float p0 = __expf(s[j][0] - mn);
            float p1 = __expf(s[j][1] - mn);
            float p2 = __expf(s[j][2] - mn8);
            float p3 = __expf(s[j][3] - mn8);
            sg += p0 + p1; sg8 += p2 + p3;
            f16 h0,l0,h1,l1,h2,l2,h3,l3;
            split2h(p0,h0,l0); split2h(p1,h1,l1); split2h(p2,h2,l2); split2h(p3,h3,l3);
            *(f162*)(smr + OFF_PH + rg  * SSTR_B + c0 * 2) = __halves2half2(h0, h1);
            *(f162*)(smr + OFF_PL + rg  * SSTR_B + c0 * 2) = __halves2half2(l0, l1);
            *(f162*)(smr + OFF_PH + rg8 * SSTR_B + c0 * 2) = __halves2half2(h2, h3);
            *(f162*)(smr + OFF_PL + rg8 * SSTR_B + c0 * 2) = __halves2half2(l2, l3);
        }
        #pragma unroll
        for (int off = 1; off <= 2; off <<= 1) {
            sg  += __shfl_xor_sync(0xffffffffu, sg,  off);
            sg8 += __shfl_xor_sync(0xffffffffu, sg8, off);
        }
        if (t == 0) { reds[wn * 64 + rg] = sg; reds[wn * 64 + rg8] = sg8; }
        #pragma unroll
        for (int j = 0; j < 4; j++) {
            o[j][0] *= al;  o[j][1] *= al;
            o[j][2] *= al8; o[j][3] *= al8;
        }
        __syncthreads();

        if (wn == 0 && lane < 16) {
            int row = wm * 16 + lane;
            float mo_r = rowm[row];
            float mn_r = fmaxf(mo_r, fmaxf(redm[row], redm[64 + row]));
            rowm[row] = mn_r;
            rowl[row] = rowl[row] * __expf(mo_r - mn_r) + reds[row] + reds[64 + row];
        }

        // ---- O += P @ V (2-term fp16) ----
        #pragma unroll
        for (int ks = 0; ks < 4; ks++) {
            uint32_t poff = (uint32_t)(wm * 16 + lr) * SSTR_B + (ks * 16 + lc * 8) * 2;
            uint32_t aPh[4], aPl[4];
            ldsm_x4(aPh, sb + OFF_PH + poff);
            ldsm_x4(aPl, sb + OFF_PL + poff);
            #pragma unroll
            for (int dp = 0; dp < 2; dp++) {
                uint32_t voff = (uint32_t)(ks * 16 + lr) * SSTR_B + (wn * 32 + dp * 16 + lc * 8) * 2;
                uint32_t bVh[4];
                ldsm_x4t(bVh, sK + TILE_B + voff);
                #pragma unroll
                for (int db = 0; db < 2; db++) {
                    float* oo = o[dp * 2 + db];
                    mma16816(oo, aPh, &bVh[db * 2]);
                    mma16816(oo, aPl, &bVh[db * 2]);
                }
            }
        }
    }
    __syncthreads();

    float li  = 1.f / rowl[rg];
    float li8 = 1.f / rowl[rg8];
    size_t ob = ((size_t)(b * SEQ + q0)) * D_MODEL + h * DHEAD;
    #pragma unroll
    for (int j = 0; j < 4; j++) {
        int c0 = wn * 32 + (j >> 1) * 16 + (j & 1) * 8 + t * 2;
        float v0 = o[j][0] * li,  v1 = o[j][1] * li;
        float v2 = o[j][2] * li8, v3 = o[j][3] * li8;
        f16 h0,l0,h1,l1,h2,l2,h3,l3;
        split2h(v0,h0,l0); split2h(v1,h1,l1); split2h(v2,h2,l2); split2h(v3,h3,l3);
        *(f162*)(Ohi + ob + (size_t)rg  * D_MODEL + c0) = __halves2half2(h0, h1);
        *(f162*)(Olo + ob + (size_t)rg  * D_MODEL + c0) = __halves2half2(l0, l1);
        *(f162*)(Ohi + ob + (size_t)rg8 * D_MODEL + c0) = __halves2half2(h2, h3);
        *(f162*)(Olo + ob + (size_t)rg8 * D_MODEL + c0) = __halves2half2(l2, l3);
    }
}

// ---------------- launch ------------------------------------------------------
extern "C" void kernel_launch(void* const* d_in, const int* in_sizes, int n_in,
                              void* d_out, int out_size) {
    const float* x    = (const float*)d_in[0];
    const int*   mask = (const int*)  d_in[1];
    const float* wq   = (const float*)d_in[2];
    const float* bq   = (const float*)d_in[3];
    const float* wk   = (const float*)d_in[4];
    const float* bk   = (const float*)d_in[5];
    const float* wv   = (const float*)d_in[6];
    const float* bv   = (const float*)d_in[7];
    const float* wo   = (const float*)d_in[8];
    const float* bo   = (const float*)d_in[9];
    const float* ln1g = (const float*)d_in[10];
    const float* ln1b = (const float*)d_in[11];
    const float* ln2g = (const float*)d_in[12];
    const float* ln2b = (const float*)d_in[13];
    const float* w1   = (const float*)d_in[14];
    const float* b1   = (const float*)d_in[15];
    const float* w2   = (const float*)d_in[16];
    const float* b2   = (const float*)d_in[17];
    float* out = (float*)d_out;

    f16 *hh, *hl, *qh, *ql, *kh, *vh, *ch, *cl, *fh, *fl;
    f16 *pwq, *pwk, *pwv, *pwo, *pw1, *pw2;
    float *px1;
    cudaGetSymbolAddress((void**)&hh, g_hh);   cudaGetSymbolAddress((void**)&hl, g_hl);
    cudaGetSymbolAddress((void**)&qh, g_qh);   cudaGetSymbolAddress((void**)&ql, g_ql);
    cudaGetSymbolAddress((void**)&kh, g_kh);   cudaGetSymbolAddress((void**)&vh, g_vh);
    cudaGetSymbolAddress((void**)&ch, g_ch);   cudaGetSymbolAddress((void**)&cl, g_cl);
    cudaGetSymbolAddress((void**)&fh, g_fh);   cudaGetSymbolAddress((void**)&fl, g_fl);
    cudaGetSymbolAddress((void**)&pwq, g_wq);  cudaGetSymbolAddress((void**)&pwk, g_wk);
    cudaGetSymbolAddress((void**)&pwv, g_wv);  cudaGetSymbolAddress((void**)&pwo, g_wo);
    cudaGetSymbolAddress((void**)&pw1, g_w1);  cudaGetSymbolAddress((void**)&pw2, g_w2);
    cudaGetSymbolAddress((void**)&px1, g_x1);

    cudaFuncSetAttribute(gemm_tc<0,0,0,1,1>, cudaFuncAttributeMaxDynamicSharedMemorySize, GEMM_SMEM);
    cudaFuncSetAttribute(gemm_tc<0,0,0,1,0>, cudaFuncAttributeMaxDynamicSharedMemorySize, GEMM_SMEM);
    cudaFuncSetAttribute(gemm_tc<0,1,1,0,0>, cudaFuncAttributeMaxDynamicSharedMemorySize, GEMM_SMEM);
    cudaFuncSetAttribute(gemm_tc<1,0,0,1,1>, cudaFuncAttributeMaxDynamicSharedMemorySize, GEMM_SMEM);
    cudaFuncSetAttribute(flash_tc, cudaFuncAttributeMaxDynamicSharedMemorySize, FLASH_SMEM);

    int n1m4 = D_MODEL * D_MODEL / 4, n4m4 = D_MODEL * FF_DIM / 4;
    cvt_kernel<<<(n1m4 + 255) / 256, 256>>>(wq, pwq, n1m4);
    cvt_kernel<<<(n1m4 + 255) / 256, 256>>>(wk, pwk, n1m4);
    cvt_kernel<<<(n1m4 + 255) / 256, 256>>>(wv, pwv, n1m4);
    cvt_kernel<<<(n1m4 + 255) / 256, 256>>>(wo, pwo, n1m4);
    cvt_kernel<<<(n4m4 + 255) / 256, 256>>>(w1, pw1, n4m4);
    cvt_kernel<<<(n4m4 + 255) / 256, 256>>>(w2, pw2, n4m4);

    // LN1 -> h hi/lo
    ln_split_kernel<<<NTOK, 256>>>(x, ln1g, ln1b, hh, hl);

    // QKV projections
    dim3 gqkv(D_MODEL / BNT, NTOK / BMT);
    gemm_tc<0,0,0,1,1><<<gqkv, 256, GEMM_SMEM>>>(hh, hl, pwq, bq, nullptr,
                                                 nullptr, qh, ql, NTOK, D_MODEL, D_MODEL);
    gemm_tc<0,0,0,1,0><<<gqkv, 256, GEMM_SMEM>>>(hh, hl, pwk, bk, nullptr,
                                                 nullptr, kh, nullptr, NTOK, D_MODEL, D_MODEL);
    gemm_tc<0,0,0,1,0><<<gqkv, 256, GEMM_SMEM>>>(hh, hl, pwv, bv, nullptr,
                                                 nullptr, vh, nullptr, NTOK, D_MODEL, D_MODEL);

    // attention -> ctx hi/lo
    dim3 gfa(SEQ / 64, 2 * NHEADS);
    flash_tc<<<gfa, 256, FLASH_SMEM>>>(qh, ql, kh, vh, mask, ch, cl);

    // O projection + residual 1 -> x1 fp32
    gemm_tc<0,1,1,0,0><<<gqkv, 256, GEMM_SMEM>>>(ch, cl, pwo, bo, x,
                                                 px1, nullptr, nullptr, NTOK, D_MODEL, D_MODEL);

    // LN2 -> h hi/lo
    ln_split_kernel<<<NTOK, 256>>>(px1, ln2g, ln2b, hh, hl);

    // FF1 (relu) -> ff hi/lo
    dim3 gff1(FF_DIM / BNT, NTOK / BMT);
    gemm_tc<1,0,0,1,1><<<gff1, 256, GEMM_SMEM>>>(hh, hl, pw1, b1, nullptr,
                                                 nullptr, fh, fl, NTOK, FF_DIM, D_MODEL);

    // FF2 + residual 2 -> out
    dim3 gff2(D_MODEL / BNT, NTOK / BMT);
    gemm_tc<0,1,1,0,0><<<gff2, 256, GEMM_SMEM>>>(fh, fl, pw2, b2, px1,
                                                 out, nullptr, nullptr, NTOK, D_MODEL, FF_DIM);
}